// round 2
// baseline (speedup 1.0000x reference)
#include <cuda_runtime.h>
#include <math.h>

#define NTOK 8192
#define DM   1024
#define DFF  4096
#define SEQ  2048
#define NB   4
#define NH   16
#define DKH  64

// ---------------- scratch (device globals: allocation-guard safe) ----------
__device__ float g_h  [(size_t)NTOK * DM];
__device__ float g_q  [(size_t)NTOK * DM];
__device__ float g_k  [(size_t)NTOK * DM];
__device__ float g_v  [(size_t)NTOK * DM];
__device__ float g_att[(size_t)NTOK * DM];
__device__ float g_x1 [(size_t)NTOK * DM];
__device__ float g_h2 [(size_t)NTOK * DM];
__device__ float g_ff [(size_t)NTOK * DFF];

// ---------------- LayerNorm: one block per row of 1024 ---------------------
__global__ void __launch_bounds__(256)
ln_kernel(const float* __restrict__ x, const float* __restrict__ gam,
          const float* __restrict__ bet, float* __restrict__ out)
{
    const int row = blockIdx.x;
    const float4 v = ((const float4*)(x + (size_t)row * DM))[threadIdx.x];
    float s = v.x + v.y + v.z + v.w;
    float q = v.x*v.x + v.y*v.y + v.z*v.z + v.w*v.w;
    #pragma unroll
    for (int o = 16; o; o >>= 1) {
        s += __shfl_xor_sync(0xffffffffu, s, o);
        q += __shfl_xor_sync(0xffffffffu, q, o);
    }
    __shared__ float ss[8], sq[8];
    const int w = threadIdx.x >> 5, l = threadIdx.x & 31;
    if (l == 0) { ss[w] = s; sq[w] = q; }
    __syncthreads();
    if (w == 0) {
        s = (l < 8) ? ss[l] : 0.f;
        q = (l < 8) ? sq[l] : 0.f;
        #pragma unroll
        for (int o = 4; o; o >>= 1) {
            s += __shfl_xor_sync(0xffffffffu, s, o);
            q += __shfl_xor_sync(0xffffffffu, q, o);
        }
        if (l == 0) { ss[0] = s; sq[0] = q; }
    }
    __syncthreads();
    const float mean = ss[0] * (1.f / DM);
    const float var  = sq[0] * (1.f / DM) - mean * mean;
    const float rstd = rsqrtf(var + 1e-5f);
    const float4 g4 = ((const float4*)gam)[threadIdx.x];
    const float4 b4 = ((const float4*)bet)[threadIdx.x];
    float4 o4;
    o4.x = (v.x - mean) * rstd * g4.x + b4.x;
    o4.y = (v.y - mean) * rstd * g4.y + b4.y;
    o4.z = (v.z - mean) * rstd * g4.z + b4.z;
    o4.w = (v.w - mean) * rstd * g4.w + b4.w;
    ((float4*)(out + (size_t)row * DM))[threadIdx.x] = o4;
}

// ---------------- fp32 SGEMM: C[N,M] = A[N,K] @ W[K,M] + bias (+act)(+res) --
__device__ __forceinline__ float gelu_exact(float v)
{
    return 0.5f * v * (1.0f + erff(v * 0.70710678118654752f));
}

// BM=128, BN=64, BK=16, 256 threads, 8x4 micro-tile per thread
template <int ACT, bool RES>
__global__ void __launch_bounds__(256)
gemm_kernel(const float* __restrict__ A, const float* __restrict__ W,
            const float* __restrict__ bias, const float* __restrict__ R,
            float* __restrict__ C, int N, int K, int M)
{
    __shared__ float As[16][128];
    __shared__ float Bs[16][64];

    const int tid = threadIdx.x;
    const int tx = tid & 15, ty = tid >> 4;
    const int m0 = blockIdx.y * 128;
    const int n0 = blockIdx.x * 64;

    float acc[8][4];
    #pragma unroll
    for (int i = 0; i < 8; i++)
        #pragma unroll
        for (int j = 0; j < 4; j++) acc[i][j] = 0.f;

    const int la_m = tid >> 1;         // 0..127
    const int la_k = (tid & 1) * 8;    // 0 or 8
    const int lb_k = tid >> 4;         // 0..15
    const int lb_n = (tid & 15) * 4;   // 0..60

    const float* Aptr = A + (size_t)(m0 + la_m) * K + la_k;
    const float* Wptr = W + (size_t)lb_k * M + n0 + lb_n;

    for (int k0 = 0; k0 < K; k0 += 16) {
        const float4 a0 = *(const float4*)(Aptr + k0);
        const float4 a1 = *(const float4*)(Aptr + k0 + 4);
        const float4 bv = *(const float4*)(Wptr + (size_t)k0 * M);

        As[la_k + 0][la_m] = a0.x;  As[la_k + 1][la_m] = a0.y;
        As[la_k + 2][la_m] = a0.z;  As[la_k + 3][la_m] = a0.w;
        As[la_k + 4][la_m] = a1.x;  As[la_k + 5][la_m] = a1.y;
        As[la_k + 6][la_m] = a1.z;  As[la_k + 7][la_m] = a1.w;
        *(float4*)&Bs[lb_k][lb_n] = bv;
        __syncthreads();

        #pragma unroll
        for (int kk = 0; kk < 16; kk++) {
            const float4 ra0 = *(const float4*)&As[kk][ty * 8];
            const float4 ra1 = *(const float4*)&As[kk][ty * 8 + 4];
            const float4 rb4 = *(const float4*)&Bs[kk][tx * 4];
            float ra[8] = {ra0.x, ra0.y, ra0.z, ra0.w, ra1.x, ra1.y, ra1.z, ra1.w};
            float rb[4] = {rb4.x, rb4.y, rb4.z, rb4.w};
            #pragma unroll
            for (int i = 0; i < 8; i++)
                #pragma unroll
                for (int j = 0; j < 4; j++)
                    acc[i][j] = fmaf(ra[i], rb[j], acc[i][j]);
        }
        __syncthreads();
    }

    const int colb = n0 + tx * 4;
    const float4 bv = *(const float4*)&bias[colb];
    #pragma unroll
    for (int i = 0; i < 8; i++) {
        const size_t row = (size_t)(m0 + ty * 8 + i);
        float4 c;
        c.x = acc[i][0] + bv.x;
        c.y = acc[i][1] + bv.y;
        c.z = acc[i][2] + bv.z;
        c.w = acc[i][3] + bv.w;
        if (ACT == 1) {
            c.x = gelu_exact(c.x); c.y = gelu_exact(c.y);
            c.z = gelu_exact(c.z); c.w = gelu_exact(c.w);
        }
        if (RES) {
            const float4 r = *(const float4*)&R[row * M + colb];
            c.x += r.x; c.y += r.y; c.z += r.z; c.w += r.w;
        }
        *(float4*)&C[row * M + colb] = c;
    }
}

// ---------------- fused flash attention (fp32, 64x64 tiles) ----------------
#define ATTN_SMEM (4 * 64 * 64 * 4 + 64 * 4)

__global__ void __launch_bounds__(256)
attn_kernel(const float* __restrict__ Q, const float* __restrict__ K,
            const float* __restrict__ V, const int* __restrict__ mask,
            float* __restrict__ O)
{
    extern __shared__ float sm[];
    float* Qs = sm;              // [d][m] transposed
    float* Ks = sm + 4096;       // [d][n] transposed
    float* Vs = sm + 8192;       // [n][d]
    float* Ps = sm + 12288;      // [m][n]
    int*   mk = (int*)(sm + 16384);

    const int tid = threadIdx.x;
    const int tx = tid & 15, ty = tid >> 4;
    const int b  = blockIdx.z, hh = blockIdx.y;
    const int q0 = blockIdx.x * 64;
    const int bS = b * SEQ;
    const int hoff = hh * DKH;

    const int lr = tid >> 2;          // 0..63
    const int lc = (tid & 3) * 16;    // 0,16,32,48

    {   // load Q tile transposed into Qs[d][m]
        const float* Qg = Q + (size_t)(bS + q0 + lr) * DM + hoff + lc;
        #pragma unroll
        for (int u = 0; u < 4; u++) {
            const float4 t = *(const float4*)(Qg + u * 4);
            Qs[(lc + u*4 + 0) * 64 + lr] = t.x;
            Qs[(lc + u*4 + 1) * 64 + lr] = t.y;
            Qs[(lc + u*4 + 2) * 64 + lr] = t.z;
            Qs[(lc + u*4 + 3) * 64 + lr] = t.w;
        }
    }

    float o[4][4];
    float m_run[4], l_run[4];
    #pragma unroll
    for (int i = 0; i < 4; i++) {
        m_run[i] = -1e30f; l_run[i] = 0.f;
        #pragma unroll
        for (int j = 0; j < 4; j++) o[i][j] = 0.f;
    }

    for (int kv0 = 0; kv0 < SEQ; kv0 += 64) {
        const float* Kg = K + (size_t)(bS + kv0 + lr) * DM + hoff + lc;
        const float* Vg = V + (size_t)(bS + kv0 + lr) * DM + hoff + lc;
        #pragma unroll
        for (int u = 0; u < 4; u++) {
            const float4 t = *(const float4*)(Kg + u * 4);
            Ks[(lc + u*4 + 0) * 64 + lr] = t.x;
            Ks[(lc + u*4 + 1) * 64 + lr] = t.y;
            Ks[(lc + u*4 + 2) * 64 + lr] = t.z;
            Ks[(lc + u*4 + 3) * 64 + lr] = t.w;
            *(float4*)(Vs + lr * 64 + lc + u * 4) = *(const float4*)(Vg + u * 4);
        }
        if (tid < 64) mk[tid] = mask[bS + kv0 + tid];
        __syncthreads();

        // S = scale * Q K^T  (per thread 4x4)
        float s4[4][4];
        #pragma unroll
        for (int i = 0; i < 4; i++)
            #pragma unroll
            for (int j = 0; j < 4; j++) s4[i][j] = 0.f;

        #pragma unroll 16
        for (int d = 0; d < 64; d++) {
            const float4 qv = *(const float4*)(Qs + d * 64 + ty * 4);
            const float4 kv = *(const float4*)(Ks + d * 64 + tx * 4);
            const float qa[4] = {qv.x, qv.y, qv.z, qv.w};
            const float ka[4] = {kv.x, kv.y, kv.z, kv.w};
            #pragma unroll
            for (int i = 0; i < 4; i++)
                #pragma unroll
                for (int j = 0; j < 4; j++)
                    s4[i][j] = fmaf(qa[i], ka[j], s4[i][j]);
        }

        // online softmax over each row (16 tx threads per row via shfl)
        #pragma unroll
        for (int i = 0; i < 4; i++) {
            float sv[4];
            float mloc = -1e30f;
            #pragma unroll
            for (int j = 0; j < 4; j++) {
                const float vv = mk[tx * 4 + j] ? s4[i][j] * 0.125f : -1e9f;
                sv[j] = vv;
                mloc = fmaxf(mloc, vv);
            }
            #pragma unroll
            for (int off = 1; off < 16; off <<= 1)
                mloc = fmaxf(mloc, __shfl_xor_sync(0xffffffffu, mloc, off));
            const float mnew  = fmaxf(m_run[i], mloc);
            const float alpha = __expf(m_run[i] - mnew);
            float p[4], lloc = 0.f;
            #pragma unroll
            for (int j = 0; j < 4; j++) { p[j] = __expf(sv[j] - mnew); lloc += p[j]; }
            #pragma unroll
            for (int off = 1; off < 16; off <<= 1)
                lloc += __shfl_xor_sync(0xffffffffu, lloc, off);
            l_run[i] = l_run[i] * alpha + lloc;
            m_run[i] = mnew;
            #pragma unroll
            for (int j = 0; j < 4; j++) o[i][j] *= alpha;
            *(float4*)(Ps + (ty * 4 + i) * 64 + tx * 4) = make_float4(p[0], p[1], p[2], p[3]);
        }
        __syncthreads();

        // O += P @ V
        #pragma unroll 8
        for (int n = 0; n < 64; n++) {
            const float4 vv = *(const float4*)(Vs + n * 64 + tx * 4);
            const float p0 = Ps[(ty * 4 + 0) * 64 + n];
            const float p1 = Ps[(ty * 4 + 1) * 64 + n];
            const float p2 = Ps[(ty * 4 + 2) * 64 + n];
            const float p3 = Ps[(ty * 4 + 3) * 64 + n];
            o[0][0] = fmaf(p0, vv.x, o[0][0]); o[0][1] = fmaf(p0, vv.y, o[0][1]);
            o[0][2] = fmaf(p0, vv.z, o[0][2]); o[0][3] = fmaf(p0, vv.w, o[0][3]);
            o[1][0] = fmaf(p1, vv.x, o[1][0]); o[1][1] = fmaf(p1, vv.y, o[1][1]);
            o[1][2] = fmaf(p1, vv.z, o[1][2]); o[1][3] = fmaf(p1, vv.w, o[1][3]);
            o[2][0] = fmaf(p2, vv.x, o[2][0]); o[2][1] = fmaf(p2, vv.y, o[2][1]);
            o[2][2] = fmaf(p2, vv.z, o[2][2]); o[2][3] = fmaf(p2, vv.w, o[2][3]);
            o[3][0] = fmaf(p3, vv.x, o[3][0]); o[3][1] = fmaf(p3, vv.y, o[3][1]);
            o[3][2] = fmaf(p3, vv.z, o[3][2]); o[3][3] = fmaf(p3, vv.w, o[3][3]);
        }
        __syncthreads();
    }

    #pragma unroll
    for (int i = 0; i < 4; i++) {
        const float inv = 1.0f / l_run[i];
        const float4 ov = make_float4(o[i][0] * inv, o[i][1] * inv,
                                      o[i][2] * inv, o[i][3] * inv);
        *(float4*)(O + (size_t)(bS + q0 + ty * 4 + i) * DM + hoff + tx * 4) = ov;
    }
}

// ---------------- launch --------------------------------------------------
extern "C" void kernel_launch(void* const* d_in, const int* in_sizes, int n_in,
                              void* d_out, int out_size)
{
    const float* x    = (const float*)d_in[0];
    const int*   mask = (const int*)  d_in[1];
    const float* Wq   = (const float*)d_in[2];
    const float* bq   = (const float*)d_in[3];
    const float* Wk   = (const float*)d_in[4];
    const float* bk   = (const float*)d_in[5];
    const float* Wv   = (const float*)d_in[6];
    const float* bv   = (const float*)d_in[7];
    const float* Wo   = (const float*)d_in[8];
    const float* bo   = (const float*)d_in[9];
    const float* W1   = (const float*)d_in[10];
    const float* b1   = (const float*)d_in[11];
    const float* W2   = (const float*)d_in[12];
    const float* b2   = (const float*)d_in[13];
    const float* g1   = (const float*)d_in[14];
    const float* be1  = (const float*)d_in[15];
    const float* g2   = (const float*)d_in[16];
    const float* be2  = (const float*)d_in[17];
    float* out = (float*)d_out;

    float *h, *q, *k, *v, *att, *x1, *h2, *ff;
    cudaGetSymbolAddress((void**)&h,   g_h);
    cudaGetSymbolAddress((void**)&q,   g_q);
    cudaGetSymbolAddress((void**)&k,   g_k);
    cudaGetSymbolAddress((void**)&v,   g_v);
    cudaGetSymbolAddress((void**)&att, g_att);
    cudaGetSymbolAddress((void**)&x1,  g_x1);
    cudaGetSymbolAddress((void**)&h2,  g_h2);
    cudaGetSymbolAddress((void**)&ff,  g_ff);

    cudaFuncSetAttribute(attn_kernel,
                         cudaFuncAttributeMaxDynamicSharedMemorySize, ATTN_SMEM);

    // h = LN1(x)
    ln_kernel<<<NTOK, 256>>>(x, g1, be1, h);
    // Q, K, V projections
    gemm_kernel<0, false><<<dim3(DM / 64, NTOK / 128), 256>>>(h, Wq, bq, nullptr, q, NTOK, DM, DM);
    gemm_kernel<0, false><<<dim3(DM / 64, NTOK / 128), 256>>>(h, Wk, bk, nullptr, k, NTOK, DM, DM);
    gemm_kernel<0, false><<<dim3(DM / 64, NTOK / 128), 256>>>(h, Wv, bv, nullptr, v, NTOK, DM, DM);
    // fused attention -> att (concat-heads layout)
    attn_kernel<<<dim3(SEQ / 64, NH, NB), 256, ATTN_SMEM>>>(q, k, v, mask, att);
    // x1 = x + att @ Wo + bo
    gemm_kernel<0, true><<<dim3(DM / 64, NTOK / 128), 256>>>(att, Wo, bo, x, x1, NTOK, DM, DM);
    // h2 = LN2(x1)
    ln_kernel<<<NTOK, 256>>>(x1, g2, be2, h2);
    // ff = gelu(h2 @ W1 + b1)
    gemm_kernel<1, false><<<dim3(DFF / 64, NTOK / 128), 256>>>(h2, W1, b1, nullptr, ff, NTOK, DM, DFF);
    // out = x1 + ff @ W2 + b2
    gemm_kernel<0, true><<<dim3(DM / 64, NTOK / 128), 256>>>(ff, W2, b2, x1, out, NTOK, DFF, DM);
}

// round 4
// speedup vs baseline: 1.8246x; 1.8246x over previous
#include <cuda_runtime.h>
#include <math.h>
#include <stdint.h>

#define NTOK 8192
#define DM   1024
#define DFF  4096
#define SEQ  2048
#define NB   4
#define NH   16
#define DKH  64

// ---------------- scratch (device globals: allocation-guard safe) ----------
__device__ float g_h  [(size_t)NTOK * DM];
__device__ float g_q  [(size_t)NTOK * DM];
__device__ float g_k  [(size_t)NTOK * DM];
__device__ float g_v  [(size_t)NTOK * DM];
__device__ float g_att[(size_t)NTOK * DM];
__device__ float g_x1 [(size_t)NTOK * DM];
__device__ float g_h2 [(size_t)NTOK * DM];
__device__ float g_ff [(size_t)NTOK * DFF];
__device__ float g_wqt[(size_t)DM * DM];
__device__ float g_wkt[(size_t)DM * DM];
__device__ float g_wvt[(size_t)DM * DM];
__device__ float g_wot[(size_t)DM * DM];
__device__ float g_w1t[(size_t)DFF * DM];
__device__ float g_w2t[(size_t)DM * DFF];

// ---------------- helpers ---------------------------------------------------
__device__ __forceinline__ uint32_t smem_u32(const void* p) {
    uint32_t a;
    asm("{ .reg .u64 t; cvta.to.shared.u64 t, %1; cvt.u32.u64 %0, t; }"
        : "=r"(a) : "l"(p));
    return a;
}
__device__ __forceinline__ void cp_async16(uint32_t dst, const void* src) {
    asm volatile("cp.async.cg.shared.global [%0], [%1], 16;" :: "r"(dst), "l"(src));
}
__device__ __forceinline__ void cp_commit() {
    asm volatile("cp.async.commit_group;" ::: "memory");
}
template <int N>
__device__ __forceinline__ void cp_wait() {
    asm volatile("cp.async.wait_group %0;" :: "n"(N) : "memory");
}
__device__ __forceinline__ uint32_t f2tf32(float f) {
    uint32_t u;
    asm("cvt.rna.tf32.f32 %0, %1;" : "=r"(u) : "f"(f));
    return u;
}
__device__ __forceinline__ void mma_tf32(float* c, const uint32_t* a, const uint32_t* b) {
    asm volatile(
        "mma.sync.aligned.m16n8k8.row.col.f32.tf32.tf32.f32 "
        "{%0,%1,%2,%3}, {%4,%5,%6,%7}, {%8,%9}, {%0,%1,%2,%3};"
        : "+f"(c[0]), "+f"(c[1]), "+f"(c[2]), "+f"(c[3])
        : "r"(a[0]), "r"(a[1]), "r"(a[2]), "r"(a[3]), "r"(b[0]), "r"(b[1]));
}
__device__ __forceinline__ float gelu_exact(float v)
{
    return 0.5f * v * (1.0f + erff(v * 0.70710678118654752f));
}

// ---------------- weight transpose  Wt[m, k] = W[k, m] ---------------------
__global__ void __launch_bounds__(256)
tr_kernel(const float* __restrict__ in, float* __restrict__ out, int rows, int cols)
{
    __shared__ float t[32][33];
    const int x  = blockIdx.x * 32 + threadIdx.x;
    const int y0 = blockIdx.y * 32;
    #pragma unroll
    for (int j = threadIdx.y; j < 32; j += 8)
        t[j][threadIdx.x] = in[(size_t)(y0 + j) * cols + x];
    __syncthreads();
    const int ox  = y0 + threadIdx.x;
    const int oy0 = blockIdx.x * 32;
    #pragma unroll
    for (int j = threadIdx.y; j < 32; j += 8)
        out[(size_t)(oy0 + j) * rows + ox] = t[threadIdx.x][j];
}

// ---------------- LayerNorm ------------------------------------------------
__global__ void __launch_bounds__(256)
ln_kernel(const float* __restrict__ x, const float* __restrict__ gam,
          const float* __restrict__ bet, float* __restrict__ out)
{
    const int row = blockIdx.x;
    const float4 v = ((const float4*)(x + (size_t)row * DM))[threadIdx.x];
    float s = v.x + v.y + v.z + v.w;
    float q = v.x*v.x + v.y*v.y + v.z*v.z + v.w*v.w;
    #pragma unroll
    for (int o = 16; o; o >>= 1) {
        s += __shfl_xor_sync(0xffffffffu, s, o);
        q += __shfl_xor_sync(0xffffffffu, q, o);
    }
    __shared__ float ss[8], sq[8];
    const int w = threadIdx.x >> 5, l = threadIdx.x & 31;
    if (l == 0) { ss[w] = s; sq[w] = q; }
    __syncthreads();
    if (w == 0) {
        s = (l < 8) ? ss[l] : 0.f;
        q = (l < 8) ? sq[l] : 0.f;
        #pragma unroll
        for (int o = 4; o; o >>= 1) {
            s += __shfl_xor_sync(0xffffffffu, s, o);
            q += __shfl_xor_sync(0xffffffffu, q, o);
        }
        if (l == 0) { ss[0] = s; sq[0] = q; }
    }
    __syncthreads();
    const float mean = ss[0] * (1.f / DM);
    const float var  = sq[0] * (1.f / DM) - mean * mean;
    const float rstd = rsqrtf(var + 1e-5f);
    const float4 g4 = ((const float4*)gam)[threadIdx.x];
    const float4 b4 = ((const float4*)bet)[threadIdx.x];
    float4 o4;
    o4.x = (v.x - mean) * rstd * g4.x + b4.x;
    o4.y = (v.y - mean) * rstd * g4.y + b4.y;
    o4.z = (v.z - mean) * rstd * g4.z + b4.z;
    o4.w = (v.w - mean) * rstd * g4.w + b4.w;
    ((float4*)(out + (size_t)row * DM))[threadIdx.x] = o4;
}

// ---------------- mma.sync tf32 GEMM ---------------------------------------
// C[NTOK, Mout] = A[NTOK, K] @ W[K, Mout] + bias (+gelu)(+res)
// Bt = W^T [Mout, K] K-major.  CTA tile 128x128, BK=16, 8 warps of 64x32.
#define SMPAD 20

template <int ACT, bool RES>
__global__ void __launch_bounds__(256, 2)
mma_gemm(const float* __restrict__ A, const float* __restrict__ Bt,
         const float* __restrict__ bias, const float* __restrict__ R,
         float* __restrict__ C, int K, int Mout)
{
    __shared__ float As[2][128][SMPAD];
    __shared__ float Bs[2][128][SMPAD];

    const int tid  = threadIdx.x;
    const int lane = tid & 31, wid = tid >> 5;
    const int wm = (wid >> 2) * 64;      // 0 / 64
    const int wn = (wid & 3) * 32;       // 0 / 32 / 64 / 96
    const int qr = lane >> 2, qc = lane & 3;
    const int m0 = blockIdx.y * 128, n0 = blockIdx.x * 128;

    float c[4][4][4];
    #pragma unroll
    for (int i = 0; i < 4; i++)
        #pragma unroll
        for (int j = 0; j < 4; j++)
            #pragma unroll
            for (int e = 0; e < 4; e++) c[i][j][e] = 0.f;

    const int lrow = tid >> 2;           // 0..63
    const int lcol = (tid & 3) * 4;      // 0,4,8,12
    const float* Ap = A  + (size_t)(m0 + lrow) * K + lcol;
    const float* Bp = Bt + (size_t)(n0 + lrow) * K + lcol;
    const size_t rstep = (size_t)64 * K;

    const int NCH = K >> 4;

    auto load_stage = [&](int buf, int ch) {
        const int koff = ch * 16;
        #pragma unroll
        for (int p = 0; p < 2; p++) {
            cp_async16(smem_u32(&As[buf][p * 64 + lrow][lcol]), Ap + p * rstep + koff);
            cp_async16(smem_u32(&Bs[buf][p * 64 + lrow][lcol]), Bp + p * rstep + koff);
        }
    };

    load_stage(0, 0);
    cp_commit();
    cp_wait<0>();
    __syncthreads();

    for (int ch = 0; ch < NCH; ch++) {
        const int buf = ch & 1;
        if (ch + 1 < NCH) { load_stage(buf ^ 1, ch + 1); cp_commit(); }

        #pragma unroll
        for (int ks = 0; ks < 16; ks += 8) {
            uint32_t a[4][4], b[4][2];
            #pragma unroll
            for (int mt = 0; mt < 4; mt++) {
                const int r = wm + mt * 16 + qr;
                a[mt][0] = f2tf32(As[buf][r    ][ks + qc]);
                a[mt][1] = f2tf32(As[buf][r + 8][ks + qc]);
                a[mt][2] = f2tf32(As[buf][r    ][ks + qc + 4]);
                a[mt][3] = f2tf32(As[buf][r + 8][ks + qc + 4]);
            }
            #pragma unroll
            for (int nt = 0; nt < 4; nt++) {
                const int nn = wn + nt * 8 + qr;
                b[nt][0] = f2tf32(Bs[buf][nn][ks + qc]);
                b[nt][1] = f2tf32(Bs[buf][nn][ks + qc + 4]);
            }
            #pragma unroll
            for (int mt = 0; mt < 4; mt++)
                #pragma unroll
                for (int nt = 0; nt < 4; nt++)
                    mma_tf32(c[mt][nt], a[mt], b[nt]);
        }

        if (ch + 1 < NCH) cp_wait<0>();
        __syncthreads();
    }

    // epilogue
    #pragma unroll
    for (int mt = 0; mt < 4; mt++) {
        #pragma unroll
        for (int half = 0; half < 2; half++) {
            const size_t grow = (size_t)(m0 + wm + mt * 16 + qr + half * 8);
            #pragma unroll
            for (int nt = 0; nt < 4; nt++) {
                const int col = n0 + wn + nt * 8 + qc * 2;
                float v0 = c[mt][nt][half * 2 + 0] + bias[col];
                float v1 = c[mt][nt][half * 2 + 1] + bias[col + 1];
                if (ACT == 1) { v0 = gelu_exact(v0); v1 = gelu_exact(v1); }
                if (RES) {
                    const float2 rv = *(const float2*)&R[grow * Mout + col];
                    v0 += rv.x; v1 += rv.y;
                }
                *(float2*)&C[grow * Mout + col] = make_float2(v0, v1);
            }
        }
    }
}

// ---------------- fused flash attention (fp32, 64x64 tiles) ----------------
#define ATTN_SMEM (4 * 64 * 64 * 4 + 64 * 4)

__global__ void __launch_bounds__(256)
attn_kernel(const float* __restrict__ Q, const float* __restrict__ K,
            const float* __restrict__ V, const int* __restrict__ mask,
            float* __restrict__ O)
{
    extern __shared__ float sm[];
    float* Qs = sm;
    float* Ks = sm + 4096;
    float* Vs = sm + 8192;
    float* Ps = sm + 12288;
    int*   mk = (int*)(sm + 16384);

    const int tid = threadIdx.x;
    const int tx = tid & 15, ty = tid >> 4;
    const int b  = blockIdx.z, hh = blockIdx.y;
    const int q0 = blockIdx.x * 64;
    const int bS = b * SEQ;
    const int hoff = hh * DKH;

    const int lr = tid >> 2;
    const int lc = (tid & 3) * 16;

    {
        const float* Qg = Q + (size_t)(bS + q0 + lr) * DM + hoff + lc;
        #pragma unroll
        for (int u = 0; u < 4; u++) {
            const float4 t = *(const float4*)(Qg + u * 4);
            Qs[(lc + u*4 + 0) * 64 + lr] = t.x;
            Qs[(lc + u*4 + 1) * 64 + lr] = t.y;
            Qs[(lc + u*4 + 2) * 64 + lr] = t.z;
            Qs[(lc + u*4 + 3) * 64 + lr] = t.w;
        }
    }

    float o[4][4];
    float m_run[4], l_run[4];
    #pragma unroll
    for (int i = 0; i < 4; i++) {
        m_run[i] = -1e30f; l_run[i] = 0.f;
        #pragma unroll
        for (int j = 0; j < 4; j++) o[i][j] = 0.f;
    }

    for (int kv0 = 0; kv0 < SEQ; kv0 += 64) {
        const float* Kg = K + (size_t)(bS + kv0 + lr) * DM + hoff + lc;
        const float* Vg = V + (size_t)(bS + kv0 + lr) * DM + hoff + lc;
        #pragma unroll
        for (int u = 0; u < 4; u++) {
            const float4 t = *(const float4*)(Kg + u * 4);
            Ks[(lc + u*4 + 0) * 64 + lr] = t.x;
            Ks[(lc + u*4 + 1) * 64 + lr] = t.y;
            Ks[(lc + u*4 + 2) * 64 + lr] = t.z;
            Ks[(lc + u*4 + 3) * 64 + lr] = t.w;
            *(float4*)(Vs + lr * 64 + lc + u * 4) = *(const float4*)(Vg + u * 4);
        }
        if (tid < 64) mk[tid] = mask[bS + kv0 + tid];
        __syncthreads();

        float s4[4][4];
        #pragma unroll
        for (int i = 0; i < 4; i++)
            #pragma unroll
            for (int j = 0; j < 4; j++) s4[i][j] = 0.f;

        #pragma unroll 16
        for (int d = 0; d < 64; d++) {
            const float4 qv = *(const float4*)(Qs + d * 64 + ty * 4);
            const float4 kv = *(const float4*)(Ks + d * 64 + tx * 4);
            const float qa[4] = {qv.x, qv.y, qv.z, qv.w};
            const float ka[4] = {kv.x, kv.y, kv.z, kv.w};
            #pragma unroll
            for (int i = 0; i < 4; i++)
                #pragma unroll
                for (int j = 0; j < 4; j++)
                    s4[i][j] = fmaf(qa[i], ka[j], s4[i][j]);
        }

        #pragma unroll
        for (int i = 0; i < 4; i++) {
            float sv[4];
            float mloc = -1e30f;
            #pragma unroll
            for (int j = 0; j < 4; j++) {
                const float vv = mk[tx * 4 + j] ? s4[i][j] * 0.125f : -1e9f;
                sv[j] = vv;
                mloc = fmaxf(mloc, vv);
            }
            #pragma unroll
            for (int off = 1; off < 16; off <<= 1)
                mloc = fmaxf(mloc, __shfl_xor_sync(0xffffffffu, mloc, off));
            const float mnew  = fmaxf(m_run[i], mloc);
            const float alpha = __expf(m_run[i] - mnew);
            float p[4], lloc = 0.f;
            #pragma unroll
            for (int j = 0; j < 4; j++) { p[j] = __expf(sv[j] - mnew); lloc += p[j]; }
            #pragma unroll
            for (int off = 1; off < 16; off <<= 1)
                lloc += __shfl_xor_sync(0xffffffffu, lloc, off);
            l_run[i] = l_run[i] * alpha + lloc;
            m_run[i] = mnew;
            #pragma unroll
            for (int j = 0; j < 4; j++) o[i][j] *= alpha;
            *(float4*)(Ps + (ty * 4 + i) * 64 + tx * 4) = make_float4(p[0], p[1], p[2], p[3]);
        }
        __syncthreads();

        #pragma unroll 8
        for (int n = 0; n < 64; n++) {
            const float4 vv = *(const float4*)(Vs + n * 64 + tx * 4);
            const float p0 = Ps[(ty * 4 + 0) * 64 + n];
            const float p1 = Ps[(ty * 4 + 1) * 64 + n];
            const float p2 = Ps[(ty * 4 + 2) * 64 + n];
            const float p3 = Ps[(ty * 4 + 3) * 64 + n];
            o[0][0] = fmaf(p0, vv.x, o[0][0]); o[0][1] = fmaf(p0, vv.y, o[0][1]);
            o[0][2] = fmaf(p0, vv.z, o[0][2]); o[0][3] = fmaf(p0, vv.w, o[0][3]);
            o[1][0] = fmaf(p1, vv.x, o[1][0]); o[1][1] = fmaf(p1, vv.y, o[1][1]);
            o[1][2] = fmaf(p1, vv.z, o[1][2]); o[1][3] = fmaf(p1, vv.w, o[1][3]);
            o[2][0] = fmaf(p2, vv.x, o[2][0]); o[2][1] = fmaf(p2, vv.y, o[2][1]);
            o[2][2] = fmaf(p2, vv.z, o[2][2]); o[2][3] = fmaf(p2, vv.w, o[2][3]);
            o[3][0] = fmaf(p3, vv.x, o[3][0]); o[3][1] = fmaf(p3, vv.y, o[3][1]);
            o[3][2] = fmaf(p3, vv.z, o[3][2]); o[3][3] = fmaf(p3, vv.w, o[3][3]);
        }
        __syncthreads();
    }

    #pragma unroll
    for (int i = 0; i < 4; i++) {
        const float inv = 1.0f / l_run[i];
        const float4 ov = make_float4(o[i][0] * inv, o[i][1] * inv,
                                      o[i][2] * inv, o[i][3] * inv);
        *(float4*)(O + (size_t)(bS + q0 + ty * 4 + i) * DM + hoff + tx * 4) = ov;
    }
}

// ---------------- launch ---------------------------------------------------
extern "C" void kernel_launch(void* const* d_in, const int* in_sizes, int n_in,
                              void* d_out, int out_size)
{
    const float* x    = (const float*)d_in[0];
    const int*   mask = (const int*)  d_in[1];
    const float* Wq   = (const float*)d_in[2];
    const float* bq   = (const float*)d_in[3];
    const float* Wk   = (const float*)d_in[4];
    const float* bk   = (const float*)d_in[5];
    const float* Wv   = (const float*)d_in[6];
    const float* bv   = (const float*)d_in[7];
    const float* Wo   = (const float*)d_in[8];
    const float* bo   = (const float*)d_in[9];
    const float* W1   = (const float*)d_in[10];
    const float* b1   = (const float*)d_in[11];
    const float* W2   = (const float*)d_in[12];
    const float* b2   = (const float*)d_in[13];
    const float* g1   = (const float*)d_in[14];
    const float* be1  = (const float*)d_in[15];
    const float* g2   = (const float*)d_in[16];
    const float* be2  = (const float*)d_in[17];
    float* out = (float*)d_out;

    float *h, *q, *k, *v, *att, *x1, *h2, *ff;
    float *wqt, *wkt, *wvt, *wot, *w1t, *w2t;
    cudaGetSymbolAddress((void**)&h,   g_h);
    cudaGetSymbolAddress((void**)&q,   g_q);
    cudaGetSymbolAddress((void**)&k,   g_k);
    cudaGetSymbolAddress((void**)&v,   g_v);
    cudaGetSymbolAddress((void**)&att, g_att);
    cudaGetSymbolAddress((void**)&x1,  g_x1);
    cudaGetSymbolAddress((void**)&h2,  g_h2);
    cudaGetSymbolAddress((void**)&ff,  g_ff);
    cudaGetSymbolAddress((void**)&wqt, g_wqt);
    cudaGetSymbolAddress((void**)&wkt, g_wkt);
    cudaGetSymbolAddress((void**)&wvt, g_wvt);
    cudaGetSymbolAddress((void**)&wot, g_wot);
    cudaGetSymbolAddress((void**)&w1t, g_w1t);
    cudaGetSymbolAddress((void**)&w2t, g_w2t);

    cudaFuncSetAttribute(attn_kernel,
                         cudaFuncAttributeMaxDynamicSharedMemorySize, ATTN_SMEM);

    const dim3 tb(32, 8);
    tr_kernel<<<dim3(DM / 32, DM / 32), tb>>>(Wq, wqt, DM, DM);
    tr_kernel<<<dim3(DM / 32, DM / 32), tb>>>(Wk, wkt, DM, DM);
    tr_kernel<<<dim3(DM / 32, DM / 32), tb>>>(Wv, wvt, DM, DM);
    tr_kernel<<<dim3(DM / 32, DM / 32), tb>>>(Wo, wot, DM, DM);
    tr_kernel<<<dim3(DFF / 32, DM / 32), tb>>>(W1, w1t, DM, DFF);
    tr_kernel<<<dim3(DM / 32, DFF / 32), tb>>>(W2, w2t, DFF, DM);

    // h = LN1(x)
    ln_kernel<<<NTOK, 256>>>(x, g1, be1, h);
    // Q, K, V projections (tf32 mma)
    mma_gemm<0, false><<<dim3(DM / 128, NTOK / 128), 256>>>(h, wqt, bq, nullptr, q, DM, DM);
    mma_gemm<0, false><<<dim3(DM / 128, NTOK / 128), 256>>>(h, wkt, bk, nullptr, k, DM, DM);
    mma_gemm<0, false><<<dim3(DM / 128, NTOK / 128), 256>>>(h, wvt, bv, nullptr, v, DM, DM);
    // fused attention
    attn_kernel<<<dim3(SEQ / 64, NH, NB), 256, ATTN_SMEM>>>(q, k, v, mask, att);
    // x1 = x + att @ Wo + bo
    mma_gemm<0, true><<<dim3(DM / 128, NTOK / 128), 256>>>(att, wot, bo, x, x1, DM, DM);
    // h2 = LN2(x1)
    ln_kernel<<<NTOK, 256>>>(x1, g2, be2, h2);
    // ff = gelu(h2 @ W1 + b1)
    mma_gemm<1, false><<<dim3(DFF / 128, NTOK / 128), 256>>>(h2, w1t, b1, nullptr, ff, DM, DFF);
    // out = x1 + ff @ W2 + b2
    mma_gemm<0, true><<<dim3(DM / 128, NTOK / 128), 256>>>(ff, w2t, b2, x1, out, DFF, DM);
}

// round 5
// speedup vs baseline: 2.5598x; 1.4030x over previous
#include <cuda_runtime.h>
#include <math.h>
#include <stdint.h>

#define NTOK 8192
#define DM   1024
#define DFF  4096
#define SEQ  2048
#define NB   4
#define NH   16
#define DKH  64

// ---------------- scratch (device globals: allocation-guard safe) ----------
__device__ float g_h  [(size_t)NTOK * DM];
__device__ float g_q  [(size_t)NTOK * DM];
__device__ float g_k  [(size_t)NTOK * DM];
__device__ float g_v  [(size_t)NTOK * DM];
__device__ float g_att[(size_t)NTOK * DM];
__device__ float g_x1 [(size_t)NTOK * DM];
__device__ float g_h2 [(size_t)NTOK * DM];
__device__ float g_ff [(size_t)NTOK * DFF];
__device__ float g_wqt[(size_t)DM * DM];
__device__ float g_wkt[(size_t)DM * DM];
__device__ float g_wvt[(size_t)DM * DM];
__device__ float g_wot[(size_t)DM * DM];
__device__ float g_w1t[(size_t)DFF * DM];
__device__ float g_w2t[(size_t)DM * DFF];

// ---------------- helpers ---------------------------------------------------
__device__ __forceinline__ uint32_t smem_u32(const void* p) {
    uint32_t a;
    asm("{ .reg .u64 t; cvta.to.shared.u64 t, %1; cvt.u32.u64 %0, t; }"
        : "=r"(a) : "l"(p));
    return a;
}
__device__ __forceinline__ void cp_async16(uint32_t dst, const void* src) {
    asm volatile("cp.async.cg.shared.global [%0], [%1], 16;" :: "r"(dst), "l"(src));
}
__device__ __forceinline__ void cp_commit() {
    asm volatile("cp.async.commit_group;" ::: "memory");
}
template <int N>
__device__ __forceinline__ void cp_wait() {
    asm volatile("cp.async.wait_group %0;" :: "n"(N) : "memory");
}
__device__ __forceinline__ uint32_t f2tf32(float f) {
    uint32_t u;
    asm("cvt.rna.tf32.f32 %0, %1;" : "=r"(u) : "f"(f));
    return u;
}
__device__ __forceinline__ void mma_tf32(float* c, const uint32_t* a, const uint32_t* b) {
    asm volatile(
        "mma.sync.aligned.m16n8k8.row.col.f32.tf32.tf32.f32 "
        "{%0,%1,%2,%3}, {%4,%5,%6,%7}, {%8,%9}, {%0,%1,%2,%3};"
        : "+f"(c[0]), "+f"(c[1]), "+f"(c[2]), "+f"(c[3])
        : "r"(a[0]), "r"(a[1]), "r"(a[2]), "r"(a[3]), "r"(b[0]), "r"(b[1]));
}
__device__ __forceinline__ float gelu_exact(float v)
{
    return 0.5f * v * (1.0f + erff(v * 0.70710678118654752f));
}

// ---------------- weight transpose  Wt[m, k] = W[k, m] ---------------------
__global__ void __launch_bounds__(256)
tr_kernel(const float* __restrict__ in, float* __restrict__ out, int rows, int cols)
{
    __shared__ float t[32][33];
    const int x  = blockIdx.x * 32 + threadIdx.x;
    const int y0 = blockIdx.y * 32;
    #pragma unroll
    for (int j = threadIdx.y; j < 32; j += 8)
        t[j][threadIdx.x] = in[(size_t)(y0 + j) * cols + x];
    __syncthreads();
    const int ox  = y0 + threadIdx.x;
    const int oy0 = blockIdx.x * 32;
    #pragma unroll
    for (int j = threadIdx.y; j < 32; j += 8)
        out[(size_t)(oy0 + j) * rows + ox] = t[threadIdx.x][j];
}

// ---------------- LayerNorm ------------------------------------------------
__global__ void __launch_bounds__(256)
ln_kernel(const float* __restrict__ x, const float* __restrict__ gam,
          const float* __restrict__ bet, float* __restrict__ out)
{
    const int row = blockIdx.x;
    const float4 v = ((const float4*)(x + (size_t)row * DM))[threadIdx.x];
    float s = v.x + v.y + v.z + v.w;
    float q = v.x*v.x + v.y*v.y + v.z*v.z + v.w*v.w;
    #pragma unroll
    for (int o = 16; o; o >>= 1) {
        s += __shfl_xor_sync(0xffffffffu, s, o);
        q += __shfl_xor_sync(0xffffffffu, q, o);
    }
    __shared__ float ss[8], sq[8];
    const int w = threadIdx.x >> 5, l = threadIdx.x & 31;
    if (l == 0) { ss[w] = s; sq[w] = q; }
    __syncthreads();
    if (w == 0) {
        s = (l < 8) ? ss[l] : 0.f;
        q = (l < 8) ? sq[l] : 0.f;
        #pragma unroll
        for (int o = 4; o; o >>= 1) {
            s += __shfl_xor_sync(0xffffffffu, s, o);
            q += __shfl_xor_sync(0xffffffffu, q, o);
        }
        if (l == 0) { ss[0] = s; sq[0] = q; }
    }
    __syncthreads();
    const float mean = ss[0] * (1.f / DM);
    const float var  = sq[0] * (1.f / DM) - mean * mean;
    const float rstd = rsqrtf(var + 1e-5f);
    const float4 g4 = ((const float4*)gam)[threadIdx.x];
    const float4 b4 = ((const float4*)bet)[threadIdx.x];
    float4 o4;
    o4.x = (v.x - mean) * rstd * g4.x + b4.x;
    o4.y = (v.y - mean) * rstd * g4.y + b4.y;
    o4.z = (v.z - mean) * rstd * g4.z + b4.z;
    o4.w = (v.w - mean) * rstd * g4.w + b4.w;
    ((float4*)(out + (size_t)row * DM))[threadIdx.x] = o4;
}

// ---------------- mma.sync tf32 GEMM ---------------------------------------
#define SMPAD 20

template <int ACT, bool RES>
__global__ void __launch_bounds__(256, 2)
mma_gemm(const float* __restrict__ A, const float* __restrict__ Bt,
         const float* __restrict__ bias, const float* __restrict__ R,
         float* __restrict__ C, int K, int Mout)
{
    __shared__ float As[2][128][SMPAD];
    __shared__ float Bs[2][128][SMPAD];

    const int tid  = threadIdx.x;
    const int lane = tid & 31, wid = tid >> 5;
    const int wm = (wid >> 2) * 64;
    const int wn = (wid & 3) * 32;
    const int qr = lane >> 2, qc = lane & 3;
    const int m0 = blockIdx.y * 128, n0 = blockIdx.x * 128;

    float c[4][4][4];
    #pragma unroll
    for (int i = 0; i < 4; i++)
        #pragma unroll
        for (int j = 0; j < 4; j++)
            #pragma unroll
            for (int e = 0; e < 4; e++) c[i][j][e] = 0.f;

    const int lrow = tid >> 2;
    const int lcol = (tid & 3) * 4;
    const float* Ap = A  + (size_t)(m0 + lrow) * K + lcol;
    const float* Bp = Bt + (size_t)(n0 + lrow) * K + lcol;
    const size_t rstep = (size_t)64 * K;

    const int NCH = K >> 4;

    auto load_stage = [&](int buf, int ch) {
        const int koff = ch * 16;
        #pragma unroll
        for (int p = 0; p < 2; p++) {
            cp_async16(smem_u32(&As[buf][p * 64 + lrow][lcol]), Ap + p * rstep + koff);
            cp_async16(smem_u32(&Bs[buf][p * 64 + lrow][lcol]), Bp + p * rstep + koff);
        }
    };

    load_stage(0, 0);
    cp_commit();
    cp_wait<0>();
    __syncthreads();

    for (int ch = 0; ch < NCH; ch++) {
        const int buf = ch & 1;
        if (ch + 1 < NCH) { load_stage(buf ^ 1, ch + 1); cp_commit(); }

        #pragma unroll
        for (int ks = 0; ks < 16; ks += 8) {
            uint32_t a[4][4], b[4][2];
            #pragma unroll
            for (int mt = 0; mt < 4; mt++) {
                const int r = wm + mt * 16 + qr;
                a[mt][0] = f2tf32(As[buf][r    ][ks + qc]);
                a[mt][1] = f2tf32(As[buf][r + 8][ks + qc]);
                a[mt][2] = f2tf32(As[buf][r    ][ks + qc + 4]);
                a[mt][3] = f2tf32(As[buf][r + 8][ks + qc + 4]);
            }
            #pragma unroll
            for (int nt = 0; nt < 4; nt++) {
                const int nn = wn + nt * 8 + qr;
                b[nt][0] = f2tf32(Bs[buf][nn][ks + qc]);
                b[nt][1] = f2tf32(Bs[buf][nn][ks + qc + 4]);
            }
            #pragma unroll
            for (int mt = 0; mt < 4; mt++)
                #pragma unroll
                for (int nt = 0; nt < 4; nt++)
                    mma_tf32(c[mt][nt], a[mt], b[nt]);
        }

        if (ch + 1 < NCH) cp_wait<0>();
        __syncthreads();
    }

    #pragma unroll
    for (int mt = 0; mt < 4; mt++) {
        #pragma unroll
        for (int half = 0; half < 2; half++) {
            const size_t grow = (size_t)(m0 + wm + mt * 16 + qr + half * 8);
            #pragma unroll
            for (int nt = 0; nt < 4; nt++) {
                const int col = n0 + wn + nt * 8 + qc * 2;
                float v0 = c[mt][nt][half * 2 + 0] + bias[col];
                float v1 = c[mt][nt][half * 2 + 1] + bias[col + 1];
                if (ACT == 1) { v0 = gelu_exact(v0); v1 = gelu_exact(v1); }
                if (RES) {
                    const float2 rv = *(const float2*)&R[grow * Mout + col];
                    v0 += rv.x; v1 += rv.y;
                }
                *(float2*)&C[grow * Mout + col] = make_float2(v0, v1);
            }
        }
    }
}

// ---------------- tf32 mma flash attention ---------------------------------
// CTA: 64 q rows, 4 warps (16 rows each), KV tiles of 64, double-buffered.
// Pitches: Q/P/K = 68 floats (4*qr+qc conflict-free), V = 72 (8*qc+qr).
#define PA 68
#define PV 72
// floats: Qs/Ps 64*68, Ks 2*64*68, Vs 2*64*72, mask 128 ints
#define ATTN_SMEM ((64 * PA + 2 * 64 * PA + 2 * 64 * PV + 128) * 4)

__global__ void __launch_bounds__(128)
attn_kernel(const float* __restrict__ Q, const float* __restrict__ K,
            const float* __restrict__ V, const int* __restrict__ mask,
            float* __restrict__ O)
{
    extern __shared__ float sm[];
    float* Qs = sm;                      // aliased as Ps after fragment preload
    float* Ks = sm + 64 * PA;
    float* Vs = Ks + 2 * 64 * PA;
    int*   mk = (int*)(Vs + 2 * 64 * PV);

    const int tid  = threadIdx.x;
    const int lane = tid & 31, wid = tid >> 5;
    const int qr = lane >> 2, qc = lane & 3;
    const int wm = wid * 16;
    const int b  = blockIdx.z, hh = blockIdx.y;
    const int q0 = blockIdx.x * 64;
    const int bS = b * SEQ;
    const int hoff = hh * DKH;

    const int lrow = tid >> 1;           // 0..63
    const int lc0  = (tid & 1) * 32;     // 0 / 32

    // ---- load Q tile (64x64) ----
    {
        const float* src = Q + (size_t)(bS + q0 + lrow) * DM + hoff + lc0;
        uint32_t dst = smem_u32(Qs + lrow * PA + lc0);
        #pragma unroll
        for (int u = 0; u < 8; u++) cp_async16(dst + u * 16, src + u * 4);
        cp_commit();
    }

    auto load_kv = [&](int buf, int kv0) {
        const float* ks = K + (size_t)(bS + kv0 + lrow) * DM + hoff + lc0;
        const float* vs = V + (size_t)(bS + kv0 + lrow) * DM + hoff + lc0;
        uint32_t dk = smem_u32(Ks + (buf * 64 + lrow) * PA + lc0);
        uint32_t dv = smem_u32(Vs + (buf * 64 + lrow) * PV + lc0);
        #pragma unroll
        for (int u = 0; u < 8; u++) {
            cp_async16(dk + u * 16, ks + u * 4);
            cp_async16(dv + u * 16, vs + u * 4);
        }
        if (tid < 16)
            cp_async16(smem_u32(mk + buf * 64 + tid * 4), mask + bS + kv0 + tid * 4);
    };

    load_kv(0, 0);
    cp_commit();
    cp_wait<0>();
    __syncthreads();

    // ---- preload Q fragments (m16 x k64 per warp) ----
    uint32_t a_q[8][4];
    #pragma unroll
    for (int ks = 0; ks < 8; ks++) {
        a_q[ks][0] = f2tf32(Qs[(wm + qr    ) * PA + ks * 8 + qc    ]);
        a_q[ks][1] = f2tf32(Qs[(wm + qr + 8) * PA + ks * 8 + qc    ]);
        a_q[ks][2] = f2tf32(Qs[(wm + qr    ) * PA + ks * 8 + qc + 4]);
        a_q[ks][3] = f2tf32(Qs[(wm + qr + 8) * PA + ks * 8 + qc + 4]);
    }
    __syncthreads();                      // Qs now reusable as Ps
    float* Ps = Qs;

    float c_o[8][4];
    #pragma unroll
    for (int nt = 0; nt < 8; nt++)
        #pragma unroll
        for (int e = 0; e < 4; e++) c_o[nt][e] = 0.f;
    float m0r = -1e30f, m1r = -1e30f, l0r = 0.f, l1r = 0.f;

    const int NT = SEQ / 64;
    for (int t = 0; t < NT; t++) {
        const int buf = t & 1;
        if (t + 1 < NT) { load_kv(buf ^ 1, (t + 1) * 64); cp_commit(); }

        // ---- S = Q K^T ----
        float c_s[8][4];
        #pragma unroll
        for (int nt = 0; nt < 8; nt++)
            #pragma unroll
            for (int e = 0; e < 4; e++) c_s[nt][e] = 0.f;

        #pragma unroll
        for (int ks = 0; ks < 8; ks++) {
            uint32_t bb[8][2];
            #pragma unroll
            for (int nt = 0; nt < 8; nt++) {
                bb[nt][0] = f2tf32(Ks[(buf * 64 + nt * 8 + qr) * PA + ks * 8 + qc    ]);
                bb[nt][1] = f2tf32(Ks[(buf * 64 + nt * 8 + qr) * PA + ks * 8 + qc + 4]);
            }
            #pragma unroll
            for (int nt = 0; nt < 8; nt++)
                mma_tf32(c_s[nt], a_q[ks], bb[nt]);
        }

        // ---- masked scale + online softmax ----
        float mx0 = -1e30f, mx1 = -1e30f;
        #pragma unroll
        for (int nt = 0; nt < 8; nt++) {
            const int c0 = nt * 8 + qc * 2;
            const float k0 = mk[buf * 64 + c0    ] ? 0.125f : 0.f;
            const float k1 = mk[buf * 64 + c0 + 1] ? 0.125f : 0.f;
            c_s[nt][0] = mk[buf * 64 + c0    ] ? c_s[nt][0] * 0.125f : -1e9f;
            c_s[nt][1] = mk[buf * 64 + c0 + 1] ? c_s[nt][1] * 0.125f : -1e9f;
            c_s[nt][2] = mk[buf * 64 + c0    ] ? c_s[nt][2] * 0.125f : -1e9f;
            c_s[nt][3] = mk[buf * 64 + c0 + 1] ? c_s[nt][3] * 0.125f : -1e9f;
            (void)k0; (void)k1;
            mx0 = fmaxf(mx0, fmaxf(c_s[nt][0], c_s[nt][1]));
            mx1 = fmaxf(mx1, fmaxf(c_s[nt][2], c_s[nt][3]));
        }
        #pragma unroll
        for (int off = 1; off < 4; off <<= 1) {
            mx0 = fmaxf(mx0, __shfl_xor_sync(0xffffffffu, mx0, off));
            mx1 = fmaxf(mx1, __shfl_xor_sync(0xffffffffu, mx1, off));
        }
        const float mn0 = fmaxf(m0r, mx0), mn1 = fmaxf(m1r, mx1);
        const float al0 = __expf(m0r - mn0), al1 = __expf(m1r - mn1);
        float s0 = 0.f, s1 = 0.f;
        #pragma unroll
        for (int nt = 0; nt < 8; nt++) {
            c_s[nt][0] = __expf(c_s[nt][0] - mn0);
            c_s[nt][1] = __expf(c_s[nt][1] - mn0);
            c_s[nt][2] = __expf(c_s[nt][2] - mn1);
            c_s[nt][3] = __expf(c_s[nt][3] - mn1);
            s0 += c_s[nt][0] + c_s[nt][1];
            s1 += c_s[nt][2] + c_s[nt][3];
        }
        #pragma unroll
        for (int off = 1; off < 4; off <<= 1) {
            s0 += __shfl_xor_sync(0xffffffffu, s0, off);
            s1 += __shfl_xor_sync(0xffffffffu, s1, off);
        }
        l0r = l0r * al0 + s0;  m0r = mn0;
        l1r = l1r * al1 + s1;  m1r = mn1;
        #pragma unroll
        for (int nt = 0; nt < 8; nt++) {
            c_o[nt][0] *= al0; c_o[nt][1] *= al0;
            c_o[nt][2] *= al1; c_o[nt][3] *= al1;
        }
        // ---- write P to per-warp smem region ----
        #pragma unroll
        for (int nt = 0; nt < 8; nt++) {
            *(float2*)&Ps[(wm + qr    ) * PA + nt * 8 + qc * 2] =
                make_float2(c_s[nt][0], c_s[nt][1]);
            *(float2*)&Ps[(wm + qr + 8) * PA + nt * 8 + qc * 2] =
                make_float2(c_s[nt][2], c_s[nt][3]);
        }
        __syncwarp();

        // ---- O += P V ----
        #pragma unroll
        for (int ks = 0; ks < 8; ks++) {
            uint32_t ap[4];
            ap[0] = f2tf32(Ps[(wm + qr    ) * PA + ks * 8 + qc    ]);
            ap[1] = f2tf32(Ps[(wm + qr + 8) * PA + ks * 8 + qc    ]);
            ap[2] = f2tf32(Ps[(wm + qr    ) * PA + ks * 8 + qc + 4]);
            ap[3] = f2tf32(Ps[(wm + qr + 8) * PA + ks * 8 + qc + 4]);
            uint32_t bb[8][2];
            #pragma unroll
            for (int nt = 0; nt < 8; nt++) {
                bb[nt][0] = f2tf32(Vs[(buf * 64 + ks * 8 + qc    ) * PV + nt * 8 + qr]);
                bb[nt][1] = f2tf32(Vs[(buf * 64 + ks * 8 + qc + 4) * PV + nt * 8 + qr]);
            }
            #pragma unroll
            for (int nt = 0; nt < 8; nt++)
                mma_tf32(c_o[nt], ap, bb[nt]);
        }
        __syncwarp();

        if (t + 1 < NT) cp_wait<0>();
        __syncthreads();
    }

    // ---- epilogue ----
    const float i0 = 1.f / l0r, i1 = 1.f / l1r;
    #pragma unroll
    for (int nt = 0; nt < 8; nt++) {
        const size_t r0 = (size_t)(bS + q0 + wm + qr);
        const int col = hoff + nt * 8 + qc * 2;
        *(float2*)&O[r0 * DM + col] =
            make_float2(c_o[nt][0] * i0, c_o[nt][1] * i0);
        *(float2*)&O[(r0 + 8) * DM + col] =
            make_float2(c_o[nt][2] * i1, c_o[nt][3] * i1);
    }
}

// ---------------- launch ---------------------------------------------------
extern "C" void kernel_launch(void* const* d_in, const int* in_sizes, int n_in,
                              void* d_out, int out_size)
{
    const float* x    = (const float*)d_in[0];
    const int*   mask = (const int*)  d_in[1];
    const float* Wq   = (const float*)d_in[2];
    const float* bq   = (const float*)d_in[3];
    const float* Wk   = (const float*)d_in[4];
    const float* bk   = (const float*)d_in[5];
    const float* Wv   = (const float*)d_in[6];
    const float* bv   = (const float*)d_in[7];
    const float* Wo   = (const float*)d_in[8];
    const float* bo   = (const float*)d_in[9];
    const float* W1   = (const float*)d_in[10];
    const float* b1   = (const float*)d_in[11];
    const float* W2   = (const float*)d_in[12];
    const float* b2   = (const float*)d_in[13];
    const float* g1   = (const float*)d_in[14];
    const float* be1  = (const float*)d_in[15];
    const float* g2   = (const float*)d_in[16];
    const float* be2  = (const float*)d_in[17];
    float* out = (float*)d_out;

    float *h, *q, *k, *v, *att, *x1, *h2, *ff;
    float *wqt, *wkt, *wvt, *wot, *w1t, *w2t;
    cudaGetSymbolAddress((void**)&h,   g_h);
    cudaGetSymbolAddress((void**)&q,   g_q);
    cudaGetSymbolAddress((void**)&k,   g_k);
    cudaGetSymbolAddress((void**)&v,   g_v);
    cudaGetSymbolAddress((void**)&att, g_att);
    cudaGetSymbolAddress((void**)&x1,  g_x1);
    cudaGetSymbolAddress((void**)&h2,  g_h2);
    cudaGetSymbolAddress((void**)&ff,  g_ff);
    cudaGetSymbolAddress((void**)&wqt, g_wqt);
    cudaGetSymbolAddress((void**)&wkt, g_wkt);
    cudaGetSymbolAddress((void**)&wvt, g_wvt);
    cudaGetSymbolAddress((void**)&wot, g_wot);
    cudaGetSymbolAddress((void**)&w1t, g_w1t);
    cudaGetSymbolAddress((void**)&w2t, g_w2t);

    cudaFuncSetAttribute(attn_kernel,
                         cudaFuncAttributeMaxDynamicSharedMemorySize, ATTN_SMEM);

    const dim3 tb(32, 8);
    tr_kernel<<<dim3(DM / 32, DM / 32), tb>>>(Wq, wqt, DM, DM);
    tr_kernel<<<dim3(DM / 32, DM / 32), tb>>>(Wk, wkt, DM, DM);
    tr_kernel<<<dim3(DM / 32, DM / 32), tb>>>(Wv, wvt, DM, DM);
    tr_kernel<<<dim3(DM / 32, DM / 32), tb>>>(Wo, wot, DM, DM);
    tr_kernel<<<dim3(DFF / 32, DM / 32), tb>>>(W1, w1t, DM, DFF);
    tr_kernel<<<dim3(DM / 32, DFF / 32), tb>>>(W2, w2t, DFF, DM);

    ln_kernel<<<NTOK, 256>>>(x, g1, be1, h);
    mma_gemm<0, false><<<dim3(DM / 128, NTOK / 128), 256>>>(h, wqt, bq, nullptr, q, DM, DM);
    mma_gemm<0, false><<<dim3(DM / 128, NTOK / 128), 256>>>(h, wkt, bk, nullptr, k, DM, DM);
    mma_gemm<0, false><<<dim3(DM / 128, NTOK / 128), 256>>>(h, wvt, bv, nullptr, v, DM, DM);
    attn_kernel<<<dim3(SEQ / 64, NH, NB), 128, ATTN_SMEM>>>(q, k, v, mask, att);
    mma_gemm<0, true><<<dim3(DM / 128, NTOK / 128), 256>>>(att, wot, bo, x, x1, DM, DM);
    ln_kernel<<<NTOK, 256>>>(x1, g2, be2, h2);
    mma_gemm<1, false><<<dim3(DFF / 128, NTOK / 128), 256>>>(h2, w1t, b1, nullptr, ff, DM, DFF);
    mma_gemm<0, true><<<dim3(DM / 128, NTOK / 128), 256>>>(ff, w2t, b2, x1, out, DFF, DM);
}

// round 6
// speedup vs baseline: 2.6433x; 1.0326x over previous
#include <cuda_runtime.h>
#include <math.h>
#include <stdint.h>

#define NTOK 8192
#define DM   1024
#define DFF  4096
#define SEQ  2048
#define NB   4
#define NH   16
#define DKH  64

// ---------------- scratch (device globals: allocation-guard safe) ----------
__device__ float g_h  [(size_t)NTOK * DM];
__device__ float g_q  [(size_t)NTOK * DM];
__device__ float g_k  [(size_t)NTOK * DM];
__device__ float g_v  [(size_t)NTOK * DM];
__device__ float g_att[(size_t)NTOK * DM];
__device__ float g_x1 [(size_t)NTOK * DM];
__device__ float g_h2 [(size_t)NTOK * DM];
__device__ float g_ff [(size_t)NTOK * DFF];
__device__ float g_wqt[(size_t)DM * DM];
__device__ float g_wkt[(size_t)DM * DM];
__device__ float g_wvt[(size_t)DM * DM];
__device__ float g_wot[(size_t)DM * DM];
__device__ float g_w1t[(size_t)DFF * DM];
__device__ float g_w2t[(size_t)DM * DFF];

// ---------------- helpers ---------------------------------------------------
__device__ __forceinline__ uint32_t smem_u32(const void* p) {
    uint32_t a;
    asm("{ .reg .u64 t; cvta.to.shared.u64 t, %1; cvt.u32.u64 %0, t; }"
        : "=r"(a) : "l"(p));
    return a;
}
__device__ __forceinline__ void cp_async16(uint32_t dst, const void* src) {
    asm volatile("cp.async.cg.shared.global [%0], [%1], 16;" :: "r"(dst), "l"(src));
}
__device__ __forceinline__ void cp_commit() {
    asm volatile("cp.async.commit_group;" ::: "memory");
}
template <int N>
__device__ __forceinline__ void cp_wait() {
    asm volatile("cp.async.wait_group %0;" :: "n"(N) : "memory");
}
__device__ __forceinline__ uint32_t f2tf32(float f) {
    uint32_t u;
    asm("cvt.rna.tf32.f32 %0, %1;" : "=r"(u) : "f"(f));
    return u;
}
__device__ __forceinline__ float round_tf32(float f) {
    return __uint_as_float(f2tf32(f));
}
__device__ __forceinline__ void mma_tf32(float* c, const uint32_t* a, const uint32_t* b) {
    asm volatile(
        "mma.sync.aligned.m16n8k8.row.col.f32.tf32.tf32.f32 "
        "{%0,%1,%2,%3}, {%4,%5,%6,%7}, {%8,%9}, {%0,%1,%2,%3};"
        : "+f"(c[0]), "+f"(c[1]), "+f"(c[2]), "+f"(c[3])
        : "r"(a[0]), "r"(a[1]), "r"(a[2]), "r"(a[3]), "r"(b[0]), "r"(b[1]));
}
__device__ __forceinline__ float gelu_exact(float v)
{
    return 0.5f * v * (1.0f + erff(v * 0.70710678118654752f));
}

// ---------------- weight transpose  Wt[m, k] = tf32(W[k, m]) ---------------
__global__ void __launch_bounds__(256)
tr_kernel(const float* __restrict__ in, float* __restrict__ out, int rows, int cols)
{
    __shared__ float t[32][33];
    const int x  = blockIdx.x * 32 + threadIdx.x;
    const int y0 = blockIdx.y * 32;
    #pragma unroll
    for (int j = threadIdx.y; j < 32; j += 8)
        t[j][threadIdx.x] = in[(size_t)(y0 + j) * cols + x];
    __syncthreads();
    const int ox  = y0 + threadIdx.x;
    const int oy0 = blockIdx.x * 32;
    #pragma unroll
    for (int j = threadIdx.y; j < 32; j += 8)
        out[(size_t)(oy0 + j) * rows + ox] = round_tf32(t[threadIdx.x][j]);
}

// ---------------- LayerNorm (tf32-rounded output; only feeds GEMMs) --------
__global__ void __launch_bounds__(256)
ln_kernel(const float* __restrict__ x, const float* __restrict__ gam,
          const float* __restrict__ bet, float* __restrict__ out)
{
    const int row = blockIdx.x;
    const float4 v = ((const float4*)(x + (size_t)row * DM))[threadIdx.x];
    float s = v.x + v.y + v.z + v.w;
    float q = v.x*v.x + v.y*v.y + v.z*v.z + v.w*v.w;
    #pragma unroll
    for (int o = 16; o; o >>= 1) {
        s += __shfl_xor_sync(0xffffffffu, s, o);
        q += __shfl_xor_sync(0xffffffffu, q, o);
    }
    __shared__ float ss[8], sq[8];
    const int w = threadIdx.x >> 5, l = threadIdx.x & 31;
    if (l == 0) { ss[w] = s; sq[w] = q; }
    __syncthreads();
    if (w == 0) {
        s = (l < 8) ? ss[l] : 0.f;
        q = (l < 8) ? sq[l] : 0.f;
        #pragma unroll
        for (int o = 4; o; o >>= 1) {
            s += __shfl_xor_sync(0xffffffffu, s, o);
            q += __shfl_xor_sync(0xffffffffu, q, o);
        }
        if (l == 0) { ss[0] = s; sq[0] = q; }
    }
    __syncthreads();
    const float mean = ss[0] * (1.f / DM);
    const float var  = sq[0] * (1.f / DM) - mean * mean;
    const float rstd = rsqrtf(var + 1e-5f);
    const float4 g4 = ((const float4*)gam)[threadIdx.x];
    const float4 b4 = ((const float4*)bet)[threadIdx.x];
    float4 o4;
    o4.x = round_tf32((v.x - mean) * rstd * g4.x + b4.x);
    o4.y = round_tf32((v.y - mean) * rstd * g4.y + b4.y);
    o4.z = round_tf32((v.z - mean) * rstd * g4.z + b4.z);
    o4.w = round_tf32((v.w - mean) * rstd * g4.w + b4.w);
    ((float4*)(out + (size_t)row * DM))[threadIdx.x] = o4;
}

// ---------------- mma.sync tf32 GEMM (3-stage cp.async pipeline) -----------
#define SMPAD 20
#define STG_F (128 * SMPAD)
#define GEMM_SMEM (3 * 2 * STG_F * 4)

template <int ACT, bool RES, bool ROUND>
__global__ void __launch_bounds__(256, 2)
mma_gemm(const float* __restrict__ A, const float* __restrict__ Bt,
         const float* __restrict__ bias, const float* __restrict__ R,
         float* __restrict__ C, int K, int Mout)
{
    extern __shared__ float dsm[];
    float* Asm = dsm;                 // 3 stages of [128][SMPAD]
    float* Bsm = dsm + 3 * STG_F;

    const int tid  = threadIdx.x;
    const int lane = tid & 31, wid = tid >> 5;
    const int wm = (wid >> 2) * 64;
    const int wn = (wid & 3) * 32;
    const int qr = lane >> 2, qc = lane & 3;
    const int m0 = blockIdx.y * 128, n0 = blockIdx.x * 128;

    float c[4][4][4];
    #pragma unroll
    for (int i = 0; i < 4; i++)
        #pragma unroll
        for (int j = 0; j < 4; j++)
            #pragma unroll
            for (int e = 0; e < 4; e++) c[i][j][e] = 0.f;

    const int lrow = tid >> 2;
    const int lcol = (tid & 3) * 4;
    const float* Ap = A  + (size_t)(m0 + lrow) * K + lcol;
    const float* Bp = Bt + (size_t)(n0 + lrow) * K + lcol;
    const size_t rstep = (size_t)64 * K;

    const int NCH = K >> 4;

    auto load_stage = [&](int st, int ch) {
        const int koff = ch * 16;
        float* as = Asm + st * STG_F;
        float* bs = Bsm + st * STG_F;
        #pragma unroll
        for (int p = 0; p < 2; p++) {
            cp_async16(smem_u32(as + (p * 64 + lrow) * SMPAD + lcol), Ap + p * rstep + koff);
            cp_async16(smem_u32(bs + (p * 64 + lrow) * SMPAD + lcol), Bp + p * rstep + koff);
        }
        cp_commit();
    };

    load_stage(0, 0);
    load_stage(1, 1);

    for (int ch = 0; ch < NCH; ch++) {
        const int buf = ch % 3;
        cp_wait<1>();
        __syncthreads();

        const float* as = Asm + buf * STG_F;
        const float* bs = Bsm + buf * STG_F;

        #pragma unroll
        for (int ks = 0; ks < 16; ks += 8) {
            uint32_t a[4][4], b[4][2];
            #pragma unroll
            for (int mt = 0; mt < 4; mt++) {
                const int r = wm + mt * 16 + qr;
                a[mt][0] = __float_as_uint(as[ r       * SMPAD + ks + qc    ]);
                a[mt][1] = __float_as_uint(as[(r + 8)  * SMPAD + ks + qc    ]);
                a[mt][2] = __float_as_uint(as[ r       * SMPAD + ks + qc + 4]);
                a[mt][3] = __float_as_uint(as[(r + 8)  * SMPAD + ks + qc + 4]);
            }
            #pragma unroll
            for (int nt = 0; nt < 4; nt++) {
                const int nn = wn + nt * 8 + qr;
                b[nt][0] = __float_as_uint(bs[nn * SMPAD + ks + qc    ]);
                b[nt][1] = __float_as_uint(bs[nn * SMPAD + ks + qc + 4]);
            }
            #pragma unroll
            for (int mt = 0; mt < 4; mt++)
                #pragma unroll
                for (int nt = 0; nt < 4; nt++)
                    mma_tf32(c[mt][nt], a[mt], b[nt]);
        }
        __syncthreads();

        if (ch + 2 < NCH) load_stage((ch + 2) % 3, ch + 2);
        else              cp_commit();      // keep group accounting uniform
    }

    #pragma unroll
    for (int mt = 0; mt < 4; mt++) {
        #pragma unroll
        for (int half = 0; half < 2; half++) {
            const size_t grow = (size_t)(m0 + wm + mt * 16 + qr + half * 8);
            #pragma unroll
            for (int nt = 0; nt < 4; nt++) {
                const int col = n0 + wn + nt * 8 + qc * 2;
                float v0 = c[mt][nt][half * 2 + 0] + bias[col];
                float v1 = c[mt][nt][half * 2 + 1] + bias[col + 1];
                if (ACT == 1) { v0 = gelu_exact(v0); v1 = gelu_exact(v1); }
                if (RES) {
                    const float2 rv = *(const float2*)&R[grow * Mout + col];
                    v0 += rv.x; v1 += rv.y;
                }
                if (ROUND) { v0 = round_tf32(v0); v1 = round_tf32(v1); }
                *(float2*)&C[grow * Mout + col] = make_float2(v0, v1);
            }
        }
    }
}

// ---------------- tf32 mma flash attention ---------------------------------
#define PA 68
#define PV 72
#define ATTN_SMEM ((64 * PA + 2 * 64 * PA + 2 * 64 * PV + 128) * 4)

__global__ void __launch_bounds__(128)
attn_kernel(const float* __restrict__ Q, const float* __restrict__ K,
            const float* __restrict__ V, const int* __restrict__ mask,
            float* __restrict__ O)
{
    extern __shared__ float sm[];
    float* Qs = sm;
    float* Ks = sm + 64 * PA;
    float* Vs = Ks + 2 * 64 * PA;
    int*   mk = (int*)(Vs + 2 * 64 * PV);

    const int tid  = threadIdx.x;
    const int lane = tid & 31, wid = tid >> 5;
    const int qr = lane >> 2, qc = lane & 3;
    const int wm = wid * 16;
    const int b  = blockIdx.z, hh = blockIdx.y;
    const int q0 = blockIdx.x * 64;
    const int bS = b * SEQ;
    const int hoff = hh * DKH;

    const int lrow = tid >> 1;
    const int lc0  = (tid & 1) * 32;

    {
        const float* src = Q + (size_t)(bS + q0 + lrow) * DM + hoff + lc0;
        uint32_t dst = smem_u32(Qs + lrow * PA + lc0);
        #pragma unroll
        for (int u = 0; u < 8; u++) cp_async16(dst + u * 16, src + u * 4);
        cp_commit();
    }

    auto load_kv = [&](int buf, int kv0) {
        const float* ks = K + (size_t)(bS + kv0 + lrow) * DM + hoff + lc0;
        const float* vs = V + (size_t)(bS + kv0 + lrow) * DM + hoff + lc0;
        uint32_t dk = smem_u32(Ks + (buf * 64 + lrow) * PA + lc0);
        uint32_t dv = smem_u32(Vs + (buf * 64 + lrow) * PV + lc0);
        #pragma unroll
        for (int u = 0; u < 8; u++) {
            cp_async16(dk + u * 16, ks + u * 4);
            cp_async16(dv + u * 16, vs + u * 4);
        }
        if (tid < 16)
            cp_async16(smem_u32(mk + buf * 64 + tid * 4), mask + bS + kv0 + tid * 4);
    };

    load_kv(0, 0);
    cp_commit();
    cp_wait<0>();
    __syncthreads();

    // Q/K/V are pre-rounded tf32 -> plain bit loads
    uint32_t a_q[8][4];
    #pragma unroll
    for (int ks = 0; ks < 8; ks++) {
        a_q[ks][0] = __float_as_uint(Qs[(wm + qr    ) * PA + ks * 8 + qc    ]);
        a_q[ks][1] = __float_as_uint(Qs[(wm + qr + 8) * PA + ks * 8 + qc    ]);
        a_q[ks][2] = __float_as_uint(Qs[(wm + qr    ) * PA + ks * 8 + qc + 4]);
        a_q[ks][3] = __float_as_uint(Qs[(wm + qr + 8) * PA + ks * 8 + qc + 4]);
    }
    __syncthreads();
    float* Ps = Qs;

    float c_o[8][4];
    #pragma unroll
    for (int nt = 0; nt < 8; nt++)
        #pragma unroll
        for (int e = 0; e < 4; e++) c_o[nt][e] = 0.f;
    float m0r = -1e30f, m1r = -1e30f, l0r = 0.f, l1r = 0.f;

    const int NT = SEQ / 64;
    for (int t = 0; t < NT; t++) {
        const int buf = t & 1;
        if (t + 1 < NT) { load_kv(buf ^ 1, (t + 1) * 64); cp_commit(); }

        float c_s[8][4];
        #pragma unroll
        for (int nt = 0; nt < 8; nt++)
            #pragma unroll
            for (int e = 0; e < 4; e++) c_s[nt][e] = 0.f;

        #pragma unroll
        for (int ks = 0; ks < 8; ks++) {
            uint32_t bb[8][2];
            #pragma unroll
            for (int nt = 0; nt < 8; nt++) {
                bb[nt][0] = __float_as_uint(Ks[(buf * 64 + nt * 8 + qr) * PA + ks * 8 + qc    ]);
                bb[nt][1] = __float_as_uint(Ks[(buf * 64 + nt * 8 + qr) * PA + ks * 8 + qc + 4]);
            }
            #pragma unroll
            for (int nt = 0; nt < 8; nt++)
                mma_tf32(c_s[nt], a_q[ks], bb[nt]);
        }

        float mx0 = -1e30f, mx1 = -1e30f;
        #pragma unroll
        for (int nt = 0; nt < 8; nt++) {
            const int c0 = nt * 8 + qc * 2;
            c_s[nt][0] = mk[buf * 64 + c0    ] ? c_s[nt][0] * 0.125f : -1e9f;
            c_s[nt][1] = mk[buf * 64 + c0 + 1] ? c_s[nt][1] * 0.125f : -1e9f;
            c_s[nt][2] = mk[buf * 64 + c0    ] ? c_s[nt][2] * 0.125f : -1e9f;
            c_s[nt][3] = mk[buf * 64 + c0 + 1] ? c_s[nt][3] * 0.125f : -1e9f;
            mx0 = fmaxf(mx0, fmaxf(c_s[nt][0], c_s[nt][1]));
            mx1 = fmaxf(mx1, fmaxf(c_s[nt][2], c_s[nt][3]));
        }
        #pragma unroll
        for (int off = 1; off < 4; off <<= 1) {
            mx0 = fmaxf(mx0, __shfl_xor_sync(0xffffffffu, mx0, off));
            mx1 = fmaxf(mx1, __shfl_xor_sync(0xffffffffu, mx1, off));
        }
        const float mn0 = fmaxf(m0r, mx0), mn1 = fmaxf(m1r, mx1);
        const float al0 = __expf(m0r - mn0), al1 = __expf(m1r - mn1);
        float s0 = 0.f, s1 = 0.f;
        #pragma unroll
        for (int nt = 0; nt < 8; nt++) {
            c_s[nt][0] = __expf(c_s[nt][0] - mn0);
            c_s[nt][1] = __expf(c_s[nt][1] - mn0);
            c_s[nt][2] = __expf(c_s[nt][2] - mn1);
            c_s[nt][3] = __expf(c_s[nt][3] - mn1);
            s0 += c_s[nt][0] + c_s[nt][1];
            s1 += c_s[nt][2] + c_s[nt][3];
        }
        #pragma unroll
        for (int off = 1; off < 4; off <<= 1) {
            s0 += __shfl_xor_sync(0xffffffffu, s0, off);
            s1 += __shfl_xor_sync(0xffffffffu, s1, off);
        }
        l0r = l0r * al0 + s0;  m0r = mn0;
        l1r = l1r * al1 + s1;  m1r = mn1;
        #pragma unroll
        for (int nt = 0; nt < 8; nt++) {
            c_o[nt][0] *= al0; c_o[nt][1] *= al0;
            c_o[nt][2] *= al1; c_o[nt][3] *= al1;
        }
        #pragma unroll
        for (int nt = 0; nt < 8; nt++) {
            *(float2*)&Ps[(wm + qr    ) * PA + nt * 8 + qc * 2] =
                make_float2(c_s[nt][0], c_s[nt][1]);
            *(float2*)&Ps[(wm + qr + 8) * PA + nt * 8 + qc * 2] =
                make_float2(c_s[nt][2], c_s[nt][3]);
        }
        __syncwarp();

        #pragma unroll
        for (int ks = 0; ks < 8; ks++) {
            uint32_t ap[4];
            ap[0] = f2tf32(Ps[(wm + qr    ) * PA + ks * 8 + qc    ]);
            ap[1] = f2tf32(Ps[(wm + qr + 8) * PA + ks * 8 + qc    ]);
            ap[2] = f2tf32(Ps[(wm + qr    ) * PA + ks * 8 + qc + 4]);
            ap[3] = f2tf32(Ps[(wm + qr + 8) * PA + ks * 8 + qc + 4]);
            uint32_t bb[8][2];
            #pragma unroll
            for (int nt = 0; nt < 8; nt++) {
                bb[nt][0] = __float_as_uint(Vs[(buf * 64 + ks * 8 + qc    ) * PV + nt * 8 + qr]);
                bb[nt][1] = __float_as_uint(Vs[(buf * 64 + ks * 8 + qc + 4) * PV + nt * 8 + qr]);
            }
            #pragma unroll
            for (int nt = 0; nt < 8; nt++)
                mma_tf32(c_o[nt], ap, bb[nt]);
        }
        __syncwarp();

        if (t + 1 < NT) cp_wait<0>();
        __syncthreads();
    }

    const float i0 = 1.f / l0r, i1 = 1.f / l1r;
    #pragma unroll
    for (int nt = 0; nt < 8; nt++) {
        const size_t r0 = (size_t)(bS + q0 + wm + qr);
        const int col = hoff + nt * 8 + qc * 2;
        *(float2*)&O[r0 * DM + col] =
            make_float2(round_tf32(c_o[nt][0] * i0), round_tf32(c_o[nt][1] * i0));
        *(float2*)&O[(r0 + 8) * DM + col] =
            make_float2(round_tf32(c_o[nt][2] * i1), round_tf32(c_o[nt][3] * i1));
    }
}

// ---------------- launch ---------------------------------------------------
extern "C" void kernel_launch(void* const* d_in, const int* in_sizes, int n_in,
                              void* d_out, int out_size)
{
    const float* x    = (const float*)d_in[0];
    const int*   mask = (const int*)  d_in[1];
    const float* Wq   = (const float*)d_in[2];
    const float* bq   = (const float*)d_in[3];
    const float* Wk   = (const float*)d_in[4];
    const float* bk   = (const float*)d_in[5];
    const float* Wv   = (const float*)d_in[6];
    const float* bv   = (const float*)d_in[7];
    const float* Wo   = (const float*)d_in[8];
    const float* bo   = (const float*)d_in[9];
    const float* W1   = (const float*)d_in[10];
    const float* b1   = (const float*)d_in[11];
    const float* W2   = (const float*)d_in[12];
    const float* b2   = (const float*)d_in[13];
    const float* g1   = (const float*)d_in[14];
    const float* be1  = (const float*)d_in[15];
    const float* g2   = (const float*)d_in[16];
    const float* be2  = (const float*)d_in[17];
    float* out = (float*)d_out;

    float *h, *q, *k, *v, *att, *x1, *h2, *ff;
    float *wqt, *wkt, *wvt, *wot, *w1t, *w2t;
    cudaGetSymbolAddress((void**)&h,   g_h);
    cudaGetSymbolAddress((void**)&q,   g_q);
    cudaGetSymbolAddress((void**)&k,   g_k);
    cudaGetSymbolAddress((void**)&v,   g_v);
    cudaGetSymbolAddress((void**)&att, g_att);
    cudaGetSymbolAddress((void**)&x1,  g_x1);
    cudaGetSymbolAddress((void**)&h2,  g_h2);
    cudaGetSymbolAddress((void**)&ff,  g_ff);
    cudaGetSymbolAddress((void**)&wqt, g_wqt);
    cudaGetSymbolAddress((void**)&wkt, g_wkt);
    cudaGetSymbolAddress((void**)&wvt, g_wvt);
    cudaGetSymbolAddress((void**)&wot, g_wot);
    cudaGetSymbolAddress((void**)&w1t, g_w1t);
    cudaGetSymbolAddress((void**)&w2t, g_w2t);

    cudaFuncSetAttribute(attn_kernel,
                         cudaFuncAttributeMaxDynamicSharedMemorySize, ATTN_SMEM);
    cudaFuncSetAttribute(mma_gemm<0, false, true>,
                         cudaFuncAttributeMaxDynamicSharedMemorySize, GEMM_SMEM);
    cudaFuncSetAttribute(mma_gemm<0, true, false>,
                         cudaFuncAttributeMaxDynamicSharedMemorySize, GEMM_SMEM);
    cudaFuncSetAttribute(mma_gemm<1, false, true>,
                         cudaFuncAttributeMaxDynamicSharedMemorySize, GEMM_SMEM);

    const dim3 tb(32, 8);
    tr_kernel<<<dim3(DM / 32, DM / 32), tb>>>(Wq, wqt, DM, DM);
    tr_kernel<<<dim3(DM / 32, DM / 32), tb>>>(Wk, wkt, DM, DM);
    tr_kernel<<<dim3(DM / 32, DM / 32), tb>>>(Wv, wvt, DM, DM);
    tr_kernel<<<dim3(DM / 32, DM / 32), tb>>>(Wo, wot, DM, DM);
    tr_kernel<<<dim3(DFF / 32, DM / 32), tb>>>(W1, w1t, DM, DFF);
    tr_kernel<<<dim3(DM / 32, DFF / 32), tb>>>(W2, w2t, DFF, DM);

    ln_kernel<<<NTOK, 256>>>(x, g1, be1, h);
    mma_gemm<0, false, true><<<dim3(DM / 128, NTOK / 128), 256, GEMM_SMEM>>>(h, wqt, bq, nullptr, q, DM, DM);
    mma_gemm<0, false, true><<<dim3(DM / 128, NTOK / 128), 256, GEMM_SMEM>>>(h, wkt, bk, nullptr, k, DM, DM);
    mma_gemm<0, false, true><<<dim3(DM / 128, NTOK / 128), 256, GEMM_SMEM>>>(h, wvt, bv, nullptr, v, DM, DM);
    attn_kernel<<<dim3(SEQ / 64, NH, NB), 128, ATTN_SMEM>>>(q, k, v, mask, att);
    mma_gemm<0, true, false><<<dim3(DM / 128, NTOK / 128), 256, GEMM_SMEM>>>(att, wot, bo, x, x1, DM, DM);
    ln_kernel<<<NTOK, 256>>>(x1, g2, be2, h2);
    mma_gemm<1, false, true><<<dim3(DFF / 128, NTOK / 128), 256, GEMM_SMEM>>>(h2, w1t, b1, nullptr, ff, DM, DFF);
    mma_gemm<0, true, false><<<dim3(DM / 128, NTOK / 128), 256, GEMM_SMEM>>>(ff, w2t, b2, x1, out, DFF, DM);
}

// round 8
// speedup vs baseline: 4.7428x; 1.7943x over previous
#include <cuda_runtime.h>
#include <cuda_fp16.h>
#include <math.h>
#include <stdint.h>

#define NTOK 8192
#define DM   1024
#define DFF  4096
#define SEQ  2048
#define NB   4
#define NH   16
#define DKH  64

// ---------------- scratch (device globals: allocation-guard safe) ----------
__device__ __half g_h  [(size_t)NTOK * DM];
__device__ __half g_q  [(size_t)NTOK * DM];
__device__ __half g_k  [(size_t)NTOK * DM];
__device__ __half g_vt [(size_t)NB * DM * SEQ];   // V transposed: [b][col][s]
__device__ __half g_att[(size_t)NTOK * DM];
__device__ float  g_x1 [(size_t)NTOK * DM];
__device__ __half g_h2 [(size_t)NTOK * DM];
__device__ __half g_ff [(size_t)NTOK * DFF];
__device__ __half g_wqt[(size_t)DM * DM];
__device__ __half g_wkt[(size_t)DM * DM];
__device__ __half g_wvt[(size_t)DM * DM];
__device__ __half g_wot[(size_t)DM * DM];
__device__ __half g_w1t[(size_t)DFF * DM];
__device__ __half g_w2t[(size_t)DM * DFF];

// ---------------- helpers ---------------------------------------------------
__device__ __forceinline__ uint32_t smem_u32(const void* p) {
    uint32_t a;
    asm("{ .reg .u64 t; cvta.to.shared.u64 t, %1; cvt.u32.u64 %0, t; }"
        : "=r"(a) : "l"(p));
    return a;
}
__device__ __forceinline__ void cp_async16(uint32_t dst, const void* src) {
    asm volatile("cp.async.cg.shared.global [%0], [%1], 16;" :: "r"(dst), "l"(src));
}
__device__ __forceinline__ void cp_commit() {
    asm volatile("cp.async.commit_group;" ::: "memory");
}
template <int N>
__device__ __forceinline__ void cp_wait() {
    asm volatile("cp.async.wait_group %0;" :: "n"(N) : "memory");
}
__device__ __forceinline__ void mma_f16(float* c, const uint32_t* a, const uint32_t* b) {
    asm volatile(
        "mma.sync.aligned.m16n8k16.row.col.f32.f16.f16.f32 "
        "{%0,%1,%2,%3}, {%4,%5,%6,%7}, {%8,%9}, {%0,%1,%2,%3};"
        : "+f"(c[0]), "+f"(c[1]), "+f"(c[2]), "+f"(c[3])
        : "r"(a[0]), "r"(a[1]), "r"(a[2]), "r"(a[3]), "r"(b[0]), "r"(b[1]));
}
__device__ __forceinline__ uint32_t pack_h2(float lo, float hi) {
    __half2 h = __floats2half2_rn(lo, hi);
    return *(uint32_t*)&h;
}
__device__ __forceinline__ float gelu_exact(float v)
{
    return 0.5f * v * (1.0f + erff(v * 0.70710678118654752f));
}

// ---------------- weight transpose  Wt[m, k] = fp16(W[k, m]) ---------------
__global__ void __launch_bounds__(256)
tr_kernel(const float* __restrict__ in, __half* __restrict__ out, int rows, int cols)
{
    __shared__ float t[32][33];
    const int x  = blockIdx.x * 32 + threadIdx.x;
    const int y0 = blockIdx.y * 32;
    #pragma unroll
    for (int j = threadIdx.y; j < 32; j += 8)
        t[j][threadIdx.x] = in[(size_t)(y0 + j) * cols + x];
    __syncthreads();
    const int ox  = y0 + threadIdx.x;
    const int oy0 = blockIdx.x * 32;
    #pragma unroll
    for (int j = threadIdx.y; j < 32; j += 8)
        out[(size_t)(oy0 + j) * rows + ox] = __float2half_rn(t[threadIdx.x][j]);
}

// ---------------- LayerNorm (fp32 in -> fp16 out; only feeds GEMMs) --------
__global__ void __launch_bounds__(256)
ln_kernel(const float* __restrict__ x, const float* __restrict__ gam,
          const float* __restrict__ bet, __half* __restrict__ out)
{
    const int row = blockIdx.x;
    const float4 v = ((const float4*)(x + (size_t)row * DM))[threadIdx.x];
    float s = v.x + v.y + v.z + v.w;
    float q = v.x*v.x + v.y*v.y + v.z*v.z + v.w*v.w;
    #pragma unroll
    for (int o = 16; o; o >>= 1) {
        s += __shfl_xor_sync(0xffffffffu, s, o);
        q += __shfl_xor_sync(0xffffffffu, q, o);
    }
    __shared__ float ss[8], sq[8];
    const int w = threadIdx.x >> 5, l = threadIdx.x & 31;
    if (l == 0) { ss[w] = s; sq[w] = q; }
    __syncthreads();
    if (w == 0) {
        s = (l < 8) ? ss[l] : 0.f;
        q = (l < 8) ? sq[l] : 0.f;
        #pragma unroll
        for (int o = 4; o; o >>= 1) {
            s += __shfl_xor_sync(0xffffffffu, s, o);
            q += __shfl_xor_sync(0xffffffffu, q, o);
        }
        if (l == 0) { ss[0] = s; sq[0] = q; }
    }
    __syncthreads();
    const float mean = ss[0] * (1.f / DM);
    const float var  = sq[0] * (1.f / DM) - mean * mean;
    const float rstd = rsqrtf(var + 1e-5f);
    const float4 g4 = ((const float4*)gam)[threadIdx.x];
    const float4 b4 = ((const float4*)bet)[threadIdx.x];
    __half2* o2 = (__half2*)(out + (size_t)row * DM);
    o2[threadIdx.x * 2    ] = __floats2half2_rn((v.x - mean) * rstd * g4.x + b4.x,
                                                (v.y - mean) * rstd * g4.y + b4.y);
    o2[threadIdx.x * 2 + 1] = __floats2half2_rn((v.z - mean) * rstd * g4.z + b4.z,
                                                (v.w - mean) * rstd * g4.w + b4.w);
}

// ---------------- fp16 mma GEMM (3-stage cp.async pipeline) ----------------
// C[NTOK, Mout] = A[NTOK, K] @ W[K, Mout] + bias (+gelu)(+res)
// A, Bt fp16 K-major. CTA 128x128, K-chunk 32, 8 warps of 64x32.
// OUT: 0 = fp32 (+residual), 1 = fp16, 2 = fp16 transposed (V path)
#define PH 40                     // halfs per smem row (80B pitch)
#define STG_H (128 * PH)          // halfs per operand per stage
#define GEMM_SMEM (3 * 2 * STG_H * 2)

template <int ACT, int OUT>
__global__ void __launch_bounds__(256, 2)
mma_gemm(const __half* __restrict__ A, const __half* __restrict__ Bt,
         const float* __restrict__ bias, const float* __restrict__ R,
         void* __restrict__ Cout, int K, int Mout)
{
    extern __shared__ __half hsm[];
    __half* Asm = hsm;
    __half* Bsm = hsm + 3 * STG_H;

    const int tid  = threadIdx.x;
    const int lane = tid & 31, wid = tid >> 5;
    const int wm = (wid >> 2) * 64;
    const int wn = (wid & 3) * 32;
    const int qr = lane >> 2, qc = lane & 3;
    const int m0 = blockIdx.y * 128, n0 = blockIdx.x * 128;

    float c[4][4][4];
    #pragma unroll
    for (int i = 0; i < 4; i++)
        #pragma unroll
        for (int j = 0; j < 4; j++)
            #pragma unroll
            for (int e = 0; e < 4; e++) c[i][j][e] = 0.f;

    const int lrow = tid >> 1;            // 0..127
    const int lseg = (tid & 1) * 16;      // halfs
    const __half* Ap = A  + (size_t)(m0 + lrow) * K + lseg;
    const __half* Bp = Bt + (size_t)(n0 + lrow) * K + lseg;

    const int NCH = K >> 5;               // K/32

    auto load_stage = [&](int st, int ch) {
        const int koff = ch * 32;
        __half* as = Asm + st * STG_H + lrow * PH + lseg;
        __half* bs = Bsm + st * STG_H + lrow * PH + lseg;
        cp_async16(smem_u32(as),     Ap + koff);
        cp_async16(smem_u32(as + 8), Ap + koff + 8);
        cp_async16(smem_u32(bs),     Bp + koff);
        cp_async16(smem_u32(bs + 8), Bp + koff + 8);
        cp_commit();
    };

    load_stage(0, 0);
    load_stage(1, 1);

    for (int ch = 0; ch < NCH; ch++) {
        const int buf = ch % 3;
        cp_wait<1>();
        __syncthreads();

        const __half* as = Asm + buf * STG_H;
        const __half* bs = Bsm + buf * STG_H;

        #pragma unroll
        for (int ks = 0; ks < 2; ks++) {
            uint32_t a[4][4], b[4][2];
            #pragma unroll
            for (int mt = 0; mt < 4; mt++) {
                const int r = wm + mt * 16 + qr;
                a[mt][0] = *(const uint32_t*)(as +  r      * PH + ks * 16 + qc * 2);
                a[mt][1] = *(const uint32_t*)(as + (r + 8) * PH + ks * 16 + qc * 2);
                a[mt][2] = *(const uint32_t*)(as +  r      * PH + ks * 16 + qc * 2 + 8);
                a[mt][3] = *(const uint32_t*)(as + (r + 8) * PH + ks * 16 + qc * 2 + 8);
            }
            #pragma unroll
            for (int nt = 0; nt < 4; nt++) {
                const int nn = wn + nt * 8 + qr;
                b[nt][0] = *(const uint32_t*)(bs + nn * PH + ks * 16 + qc * 2);
                b[nt][1] = *(const uint32_t*)(bs + nn * PH + ks * 16 + qc * 2 + 8);
            }
            #pragma unroll
            for (int mt = 0; mt < 4; mt++)
                #pragma unroll
                for (int nt = 0; nt < 4; nt++)
                    mma_f16(c[mt][nt], a[mt], b[nt]);
        }
        __syncthreads();

        if (ch + 2 < NCH) load_stage((ch + 2) % 3, ch + 2);
        else              cp_commit();
    }

    // epilogue
    #pragma unroll
    for (int mt = 0; mt < 4; mt++) {
        #pragma unroll
        for (int half_ = 0; half_ < 2; half_++) {
            const int gm = m0 + wm + mt * 16 + qr + half_ * 8;
            #pragma unroll
            for (int nt = 0; nt < 4; nt++) {
                const int col = n0 + wn + nt * 8 + qc * 2;
                float v0 = c[mt][nt][half_ * 2 + 0] + bias[col];
                float v1 = c[mt][nt][half_ * 2 + 1] + bias[col + 1];
                if (ACT == 1) { v0 = gelu_exact(v0); v1 = gelu_exact(v1); }
                if (OUT == 0) {
                    const float2 rv = *(const float2*)&R[(size_t)gm * Mout + col];
                    *(float2*)((float*)Cout + (size_t)gm * Mout + col) =
                        make_float2(v0 + rv.x, v1 + rv.y);
                } else if (OUT == 1) {
                    *(__half2*)((__half*)Cout + (size_t)gm * Mout + col) =
                        __floats2half2_rn(v0, v1);
                } else {
                    // transposed V: vt[b][col][s], b = gm>>11, s = gm&2047
                    const int bb = gm >> 11, s = gm & 2047;
                    __half* vt = (__half*)Cout;
                    vt[((size_t)bb * DM + col    ) * SEQ + s] = __float2half_rn(v0);
                    vt[((size_t)bb * DM + col + 1) * SEQ + s] = __float2half_rn(v1);
                }
            }
        }
    }
}

// ---------------- fp16 mma flash attention ---------------------------------
// CTA: 64 q rows, 4 warps (16 rows each), KV tiles of 64, double-buffered.
// Tiles: Qs/Ks [row][dk] pitch 72 halfs; Vs = V^T [dk][kv] pitch 72 halfs.
#define PT 72
#define T_H (64 * PT)
#define ATTN_SMEM ((T_H + 2 * T_H + 2 * T_H) * 2 + 2 * 64 * 4)

__global__ void __launch_bounds__(128)
attn_kernel(const __half* __restrict__ Q, const __half* __restrict__ K,
            const __half* __restrict__ Vt, const int* __restrict__ mask,
            __half* __restrict__ O)
{
    extern __shared__ __half asm_[];
    __half* Qs = asm_;
    __half* Ks = asm_ + T_H;
    __half* Vs = asm_ + 3 * T_H;
    int*    mk = (int*)(asm_ + 5 * T_H);

    const int tid  = threadIdx.x;
    const int lane = tid & 31, wid = tid >> 5;
    const int qr = lane >> 2, qc = lane & 3;
    const int wm = wid * 16;
    const int b  = blockIdx.z, hh = blockIdx.y;
    const int q0 = blockIdx.x * 64;
    const int bS = b * SEQ;
    const int hoff = hh * DKH;

    const int lrow = tid >> 1;            // 0..63
    const int lseg = (tid & 1) * 32;      // halfs

    {
        const __half* src = Q + (size_t)(bS + q0 + lrow) * DM + hoff + lseg;
        uint32_t dst = smem_u32(Qs + lrow * PT + lseg);
        #pragma unroll
        for (int u = 0; u < 4; u++) cp_async16(dst + u * 16, src + u * 8);
        cp_commit();
    }

    // V^T base for this (batch, head): vt[b][col][s] with col stride SEQ
    const __half* VtBase = Vt + ((size_t)b * DM + hoff) * SEQ;

    auto load_kv = [&](int buf, int kv0) {
        const __half* ks = K + (size_t)(bS + kv0 + lrow) * DM + hoff + lseg;
        const __half* vs = VtBase + (size_t)lrow * SEQ + kv0 + lseg;
        uint32_t dk = smem_u32(Ks + buf * T_H + lrow * PT + lseg);
        uint32_t dv = smem_u32(Vs + buf * T_H + lrow * PT + lseg);
        #pragma unroll
        for (int u = 0; u < 4; u++) {
            cp_async16(dk + u * 16, ks + u * 8);
            cp_async16(dv + u * 16, vs + u * 8);
        }
        if (tid < 16)
            cp_async16(smem_u32(mk + buf * 64 + tid * 4), mask + bS + kv0 + tid * 4);
    };

    load_kv(0, 0);
    cp_commit();
    cp_wait<0>();
    __syncthreads();

    // preload Q fragments: 4 k16-steps over dk=64
    uint32_t a_q[4][4];
    #pragma unroll
    for (int ks = 0; ks < 4; ks++) {
        a_q[ks][0] = *(const uint32_t*)(Qs + (wm + qr    ) * PT + ks * 16 + qc * 2);
        a_q[ks][1] = *(const uint32_t*)(Qs + (wm + qr + 8) * PT + ks * 16 + qc * 2);
        a_q[ks][2] = *(const uint32_t*)(Qs + (wm + qr    ) * PT + ks * 16 + qc * 2 + 8);
        a_q[ks][3] = *(const uint32_t*)(Qs + (wm + qr + 8) * PT + ks * 16 + qc * 2 + 8);
    }

    float c_o[8][4];
    #pragma unroll
    for (int nt = 0; nt < 8; nt++)
        #pragma unroll
        for (int e = 0; e < 4; e++) c_o[nt][e] = 0.f;
    float m0r = -1e30f, m1r = -1e30f, l0r = 0.f, l1r = 0.f;

    const int NT = SEQ / 64;
    for (int t = 0; t < NT; t++) {
        const int buf = t & 1;
        if (t + 1 < NT) { load_kv(buf ^ 1, (t + 1) * 64); cp_commit(); }

        // ---- S = Q K^T ----
        float c_s[8][4];
        #pragma unroll
        for (int nt = 0; nt < 8; nt++)
            #pragma unroll
            for (int e = 0; e < 4; e++) c_s[nt][e] = 0.f;

        const __half* kb = Ks + buf * T_H;
        #pragma unroll
        for (int ks = 0; ks < 4; ks++) {
            uint32_t bb[8][2];
            #pragma unroll
            for (int nt = 0; nt < 8; nt++) {
                bb[nt][0] = *(const uint32_t*)(kb + (nt * 8 + qr) * PT + ks * 16 + qc * 2);
                bb[nt][1] = *(const uint32_t*)(kb + (nt * 8 + qr) * PT + ks * 16 + qc * 2 + 8);
            }
            #pragma unroll
            for (int nt = 0; nt < 8; nt++)
                mma_f16(c_s[nt], a_q[ks], bb[nt]);
        }

        // ---- masked scale + online softmax ----
        float mx0 = -1e30f, mx1 = -1e30f;
        #pragma unroll
        for (int nt = 0; nt < 8; nt++) {
            const int c0 = nt * 8 + qc * 2;
            c_s[nt][0] = mk[buf * 64 + c0    ] ? c_s[nt][0] * 0.125f : -1e9f;
            c_s[nt][1] = mk[buf * 64 + c0 + 1] ? c_s[nt][1] * 0.125f : -1e9f;
            c_s[nt][2] = mk[buf * 64 + c0    ] ? c_s[nt][2] * 0.125f : -1e9f;
            c_s[nt][3] = mk[buf * 64 + c0 + 1] ? c_s[nt][3] * 0.125f : -1e9f;
            mx0 = fmaxf(mx0, fmaxf(c_s[nt][0], c_s[nt][1]));
            mx1 = fmaxf(mx1, fmaxf(c_s[nt][2], c_s[nt][3]));
        }
        #pragma unroll
        for (int off = 1; off < 4; off <<= 1) {
            mx0 = fmaxf(mx0, __shfl_xor_sync(0xffffffffu, mx0, off));
            mx1 = fmaxf(mx1, __shfl_xor_sync(0xffffffffu, mx1, off));
        }
        const float mn0 = fmaxf(m0r, mx0), mn1 = fmaxf(m1r, mx1);
        const float al0 = __expf(m0r - mn0), al1 = __expf(m1r - mn1);
        float s0 = 0.f, s1 = 0.f;
        #pragma unroll
        for (int nt = 0; nt < 8; nt++) {
            c_s[nt][0] = __expf(c_s[nt][0] - mn0);
            c_s[nt][1] = __expf(c_s[nt][1] - mn0);
            c_s[nt][2] = __expf(c_s[nt][2] - mn1);
            c_s[nt][3] = __expf(c_s[nt][3] - mn1);
            s0 += c_s[nt][0] + c_s[nt][1];
            s1 += c_s[nt][2] + c_s[nt][3];
        }
        #pragma unroll
        for (int off = 1; off < 4; off <<= 1) {
            s0 += __shfl_xor_sync(0xffffffffu, s0, off);
            s1 += __shfl_xor_sync(0xffffffffu, s1, off);
        }
        l0r = l0r * al0 + s0;  m0r = mn0;
        l1r = l1r * al1 + s1;  m1r = mn1;
        #pragma unroll
        for (int nt = 0; nt < 8; nt++) {
            c_o[nt][0] *= al0; c_o[nt][1] *= al0;
            c_o[nt][2] *= al1; c_o[nt][3] *= al1;
        }

        // ---- P fragments (pure register pack: C-frag -> A-frag) ----
        uint32_t ap[4][4];
        #pragma unroll
        for (int ks = 0; ks < 4; ks++) {
            ap[ks][0] = pack_h2(c_s[2*ks    ][0], c_s[2*ks    ][1]);
            ap[ks][1] = pack_h2(c_s[2*ks    ][2], c_s[2*ks    ][3]);
            ap[ks][2] = pack_h2(c_s[2*ks + 1][0], c_s[2*ks + 1][1]);
            ap[ks][3] = pack_h2(c_s[2*ks + 1][2], c_s[2*ks + 1][3]);
        }

        // ---- O += P V  (V^T tiles: [dk][kv]) ----
        const __half* vb = Vs + buf * T_H;
        #pragma unroll
        for (int ks = 0; ks < 4; ks++) {
            uint32_t bb[8][2];
            #pragma unroll
            for (int nt = 0; nt < 8; nt++) {
                bb[nt][0] = *(const uint32_t*)(vb + (nt * 8 + qr) * PT + ks * 16 + qc * 2);
                bb[nt][1] = *(const uint32_t*)(vb + (nt * 8 + qr) * PT + ks * 16 + qc * 2 + 8);
            }
            #pragma unroll
            for (int nt = 0; nt < 8; nt++)
                mma_f16(c_o[nt], ap[ks], bb[nt]);
        }

        if (t + 1 < NT) cp_wait<0>();
        __syncthreads();
    }

    // ---- epilogue (fp16 att output) ----
    const float i0 = 1.f / l0r, i1 = 1.f / l1r;
    #pragma unroll
    for (int nt = 0; nt < 8; nt++) {
        const size_t r0 = (size_t)(bS + q0 + wm + qr);
        const int col = hoff + nt * 8 + qc * 2;
        *(__half2*)&O[r0 * DM + col] =
            __floats2half2_rn(c_o[nt][0] * i0, c_o[nt][1] * i0);
        *(__half2*)&O[(r0 + 8) * DM + col] =
            __floats2half2_rn(c_o[nt][2] * i1, c_o[nt][3] * i1);
    }
}

// ---------------- launch ---------------------------------------------------
extern "C" void kernel_launch(void* const* d_in, const int* in_sizes, int n_in,
                              void* d_out, int out_size)
{
    const float* x    = (const float*)d_in[0];
    const int*   mask = (const int*)  d_in[1];
    const float* Wq   = (const float*)d_in[2];
    const float* bq   = (const float*)d_in[3];
    const float* Wk   = (const float*)d_in[4];
    const float* bk   = (const float*)d_in[5];
    const float* Wv   = (const float*)d_in[6];
    const float* bv   = (const float*)d_in[7];
    const float* Wo   = (const float*)d_in[8];
    const float* bo   = (const float*)d_in[9];
    const float* W1   = (const float*)d_in[10];
    const float* b1   = (const float*)d_in[11];
    const float* W2   = (const float*)d_in[12];
    const float* b2   = (const float*)d_in[13];
    const float* g1   = (const float*)d_in[14];
    const float* be1  = (const float*)d_in[15];
    const float* g2   = (const float*)d_in[16];
    const float* be2  = (const float*)d_in[17];
    float* out = (float*)d_out;

    __half *h, *q, *k, *vt, *att, *h2, *ff;
    float  *x1;
    __half *wqt, *wkt, *wvt, *wot, *w1t, *w2t;
    cudaGetSymbolAddress((void**)&h,   g_h);
    cudaGetSymbolAddress((void**)&q,   g_q);
    cudaGetSymbolAddress((void**)&k,   g_k);
    cudaGetSymbolAddress((void**)&vt,  g_vt);
    cudaGetSymbolAddress((void**)&att, g_att);
    cudaGetSymbolAddress((void**)&x1,  g_x1);
    cudaGetSymbolAddress((void**)&h2,  g_h2);
    cudaGetSymbolAddress((void**)&ff,  g_ff);
    cudaGetSymbolAddress((void**)&wqt, g_wqt);
    cudaGetSymbolAddress((void**)&wkt, g_wkt);
    cudaGetSymbolAddress((void**)&wvt, g_wvt);
    cudaGetSymbolAddress((void**)&wot, g_wot);
    cudaGetSymbolAddress((void**)&w1t, g_w1t);
    cudaGetSymbolAddress((void**)&w2t, g_w2t);

    cudaFuncSetAttribute(attn_kernel,
                         cudaFuncAttributeMaxDynamicSharedMemorySize, ATTN_SMEM);
    cudaFuncSetAttribute(mma_gemm<0, 0>,
                         cudaFuncAttributeMaxDynamicSharedMemorySize, GEMM_SMEM);
    cudaFuncSetAttribute(mma_gemm<0, 1>,
                         cudaFuncAttributeMaxDynamicSharedMemorySize, GEMM_SMEM);
    cudaFuncSetAttribute(mma_gemm<0, 2>,
                         cudaFuncAttributeMaxDynamicSharedMemorySize, GEMM_SMEM);
    cudaFuncSetAttribute(mma_gemm<1, 1>,
                         cudaFuncAttributeMaxDynamicSharedMemorySize, GEMM_SMEM);

    const dim3 tb(32, 8);
    tr_kernel<<<dim3(DM / 32, DM / 32), tb>>>(Wq, wqt, DM, DM);
    tr_kernel<<<dim3(DM / 32, DM / 32), tb>>>(Wk, wkt, DM, DM);
    tr_kernel<<<dim3(DM / 32, DM / 32), tb>>>(Wv, wvt, DM, DM);
    tr_kernel<<<dim3(DM / 32, DM / 32), tb>>>(Wo, wot, DM, DM);
    tr_kernel<<<dim3(DFF / 32, DM / 32), tb>>>(W1, w1t, DM, DFF);
    tr_kernel<<<dim3(DM / 32, DFF / 32), tb>>>(W2, w2t, DFF, DM);

    ln_kernel<<<NTOK, 256>>>(x, g1, be1, h);
    mma_gemm<0, 1><<<dim3(DM / 128, NTOK / 128), 256, GEMM_SMEM>>>(h, wqt, bq, nullptr, q, DM, DM);
    mma_gemm<0, 1><<<dim3(DM / 128, NTOK / 128), 256, GEMM_SMEM>>>(h, wkt, bk, nullptr, k, DM, DM);
    mma_gemm<0, 2><<<dim3(DM / 128, NTOK / 128), 256, GEMM_SMEM>>>(h, wvt, bv, nullptr, vt, DM, DM);
    attn_kernel<<<dim3(SEQ / 64, NH, NB), 128, ATTN_SMEM>>>(q, k, vt, mask, att);
    mma_gemm<0, 0><<<dim3(DM / 128, NTOK / 128), 256, GEMM_SMEM>>>(att, wot, bo, x, x1, DM, DM);
    ln_kernel<<<NTOK, 256>>>(x1, g2, be2, h2);
    mma_gemm<1, 1><<<dim3(DFF / 128, NTOK / 128), 256, GEMM_SMEM>>>(h2, w1t, b1, nullptr, ff, DM, DFF);
    mma_gemm<0, 0><<<dim3(DM / 128, NTOK / 128), 256, GEMM_SMEM>>>(ff, w2t, b2, x1, out, DFF, DM);
}

// round 9
// speedup vs baseline: 5.2949x; 1.1164x over previous
#include <cuda_runtime.h>
#include <cuda_fp16.h>
#include <math.h>
#include <stdint.h>

#define NTOK 8192
#define DM   1024
#define DFF  4096
#define SEQ  2048
#define NB   4
#define NH   16
#define DKH  64

// ---------------- scratch (device globals: allocation-guard safe) ----------
__device__ __half g_h  [(size_t)NTOK * DM];
__device__ __half g_q  [(size_t)NTOK * DM];
__device__ __half g_k  [(size_t)NTOK * DM];
__device__ __half g_vt [(size_t)NB * DM * SEQ];   // V transposed: [b][col][s]
__device__ __half g_att[(size_t)NTOK * DM];
__device__ float  g_x1 [(size_t)NTOK * DM];
__device__ __half g_h2 [(size_t)NTOK * DM];
__device__ __half g_ff [(size_t)NTOK * DFF];
__device__ __half g_wqt[(size_t)DM * DM];
__device__ __half g_wkt[(size_t)DM * DM];
__device__ __half g_wvt[(size_t)DM * DM];
__device__ __half g_wot[(size_t)DM * DM];
__device__ __half g_w1t[(size_t)DFF * DM];
__device__ __half g_w2t[(size_t)DM * DFF];

// ---------------- helpers ---------------------------------------------------
__device__ __forceinline__ uint32_t smem_u32(const void* p) {
    uint32_t a;
    asm("{ .reg .u64 t; cvta.to.shared.u64 t, %1; cvt.u32.u64 %0, t; }"
        : "=r"(a) : "l"(p));
    return a;
}
__device__ __forceinline__ void cp_async16(uint32_t dst, const void* src) {
    asm volatile("cp.async.cg.shared.global [%0], [%1], 16;" :: "r"(dst), "l"(src));
}
__device__ __forceinline__ void cp_commit() {
    asm volatile("cp.async.commit_group;" ::: "memory");
}
template <int N>
__device__ __forceinline__ void cp_wait() {
    asm volatile("cp.async.wait_group %0;" :: "n"(N) : "memory");
}
__device__ __forceinline__ void ldmatrix_x4(uint32_t* r, uint32_t addr) {
    asm volatile("ldmatrix.sync.aligned.m8n8.x4.shared.b16 {%0,%1,%2,%3}, [%4];"
                 : "=r"(r[0]), "=r"(r[1]), "=r"(r[2]), "=r"(r[3]) : "r"(addr));
}
__device__ __forceinline__ void mma_f16(float* c, const uint32_t* a, const uint32_t* b) {
    asm volatile(
        "mma.sync.aligned.m16n8k16.row.col.f32.f16.f16.f32 "
        "{%0,%1,%2,%3}, {%4,%5,%6,%7}, {%8,%9}, {%0,%1,%2,%3};"
        : "+f"(c[0]), "+f"(c[1]), "+f"(c[2]), "+f"(c[3])
        : "r"(a[0]), "r"(a[1]), "r"(a[2]), "r"(a[3]), "r"(b[0]), "r"(b[1]));
}
__device__ __forceinline__ uint32_t pack_h2(float lo, float hi) {
    __half2 h = __floats2half2_rn(lo, hi);
    return *(uint32_t*)&h;
}
__device__ __forceinline__ float gelu_exact(float v)
{
    return 0.5f * v * (1.0f + erff(v * 0.70710678118654752f));
}

// ---------------- weight transpose  Wt[m, k] = fp16(W[k, m]) ---------------
__global__ void __launch_bounds__(256)
tr_kernel(const float* __restrict__ in, __half* __restrict__ out, int rows, int cols)
{
    __shared__ float t[32][33];
    const int x  = blockIdx.x * 32 + threadIdx.x;
    const int y0 = blockIdx.y * 32;
    #pragma unroll
    for (int j = threadIdx.y; j < 32; j += 8)
        t[j][threadIdx.x] = in[(size_t)(y0 + j) * cols + x];
    __syncthreads();
    const int ox  = y0 + threadIdx.x;
    const int oy0 = blockIdx.x * 32;
    #pragma unroll
    for (int j = threadIdx.y; j < 32; j += 8)
        out[(size_t)(oy0 + j) * rows + ox] = __float2half_rn(t[threadIdx.x][j]);
}

// ---------------- LayerNorm (fp32 in -> fp16 out; only feeds GEMMs) --------
__global__ void __launch_bounds__(256)
ln_kernel(const float* __restrict__ x, const float* __restrict__ gam,
          const float* __restrict__ bet, __half* __restrict__ out)
{
    const int row = blockIdx.x;
    const float4 v = ((const float4*)(x + (size_t)row * DM))[threadIdx.x];
    float s = v.x + v.y + v.z + v.w;
    float q = v.x*v.x + v.y*v.y + v.z*v.z + v.w*v.w;
    #pragma unroll
    for (int o = 16; o; o >>= 1) {
        s += __shfl_xor_sync(0xffffffffu, s, o);
        q += __shfl_xor_sync(0xffffffffu, q, o);
    }
    __shared__ float ss[8], sq[8];
    const int w = threadIdx.x >> 5, l = threadIdx.x & 31;
    if (l == 0) { ss[w] = s; sq[w] = q; }
    __syncthreads();
    if (w == 0) {
        s = (l < 8) ? ss[l] : 0.f;
        q = (l < 8) ? sq[l] : 0.f;
        #pragma unroll
        for (int o = 4; o; o >>= 1) {
            s += __shfl_xor_sync(0xffffffffu, s, o);
            q += __shfl_xor_sync(0xffffffffu, q, o);
        }
        if (l == 0) { ss[0] = s; sq[0] = q; }
    }
    __syncthreads();
    const float mean = ss[0] * (1.f / DM);
    const float var  = sq[0] * (1.f / DM) - mean * mean;
    const float rstd = rsqrtf(var + 1e-5f);
    const float4 g4 = ((const float4*)gam)[threadIdx.x];
    const float4 b4 = ((const float4*)bet)[threadIdx.x];
    __half2* o2 = (__half2*)(out + (size_t)row * DM);
    o2[threadIdx.x * 2    ] = __floats2half2_rn((v.x - mean) * rstd * g4.x + b4.x,
                                                (v.y - mean) * rstd * g4.y + b4.y);
    o2[threadIdx.x * 2 + 1] = __floats2half2_rn((v.z - mean) * rstd * g4.z + b4.z,
                                                (v.w - mean) * rstd * g4.w + b4.w);
}

// ---------------- fp16 mma GEMM (3-stage cp.async + ldmatrix) --------------
// C[NTOK, Mout] = A[NTOK, K] @ W[K, Mout] + bias (+gelu)(+res)
// A, Bt fp16 K-major. CTA 128x128, K-chunk 32, 8 warps of 64x32.
// OUT: 0 = fp32 (+residual), 1 = fp16, 2 = fp16 transposed (V path)
#define PH 40                     // halfs per smem row (80B pitch; ldmatrix conflict-free)
#define STG_H (128 * PH)          // halfs per operand per stage
#define GEMM_SMEM (3 * 2 * STG_H * 2)

template <int ACT, int OUT>
__global__ void __launch_bounds__(256, 2)
mma_gemm(const __half* __restrict__ A, const __half* __restrict__ Bt,
         const float* __restrict__ bias, const float* __restrict__ R,
         void* __restrict__ Cout, int K, int Mout)
{
    extern __shared__ __half hsm[];
    __half* Asm = hsm;
    __half* Bsm = hsm + 3 * STG_H;

    const int tid  = threadIdx.x;
    const int lane = tid & 31, wid = tid >> 5;
    const int wm = (wid >> 2) * 64;
    const int wn = (wid & 3) * 32;
    const int qr = lane >> 2, qc = lane & 3;
    const int lm8 = lane >> 3;            // ldmatrix matrix index
    const int l8  = lane & 7;             // ldmatrix row within matrix
    const int m0 = blockIdx.y * 128, n0 = blockIdx.x * 128;

    float c[4][4][4];
    #pragma unroll
    for (int i = 0; i < 4; i++)
        #pragma unroll
        for (int j = 0; j < 4; j++)
            #pragma unroll
            for (int e = 0; e < 4; e++) c[i][j][e] = 0.f;

    const int lrow = tid >> 1;            // 0..127
    const int lseg = (tid & 1) * 16;      // halfs
    const __half* Ap = A  + (size_t)(m0 + lrow) * K + lseg;
    const __half* Bp = Bt + (size_t)(n0 + lrow) * K + lseg;

    const int NCH = K >> 5;               // K/32

    auto load_stage = [&](int st, int ch) {
        const int koff = ch * 32;
        __half* as = Asm + st * STG_H + lrow * PH + lseg;
        __half* bs = Bsm + st * STG_H + lrow * PH + lseg;
        cp_async16(smem_u32(as),     Ap + koff);
        cp_async16(smem_u32(as + 8), Ap + koff + 8);
        cp_async16(smem_u32(bs),     Bp + koff);
        cp_async16(smem_u32(bs + 8), Bp + koff + 8);
        cp_commit();
    };

    load_stage(0, 0);
    load_stage(1, 1);

    // ldmatrix per-lane row/col offsets
    const int a_ro = ((lm8 & 1) << 3) + l8;   // row offset within m16 tile
    const int a_co = (lm8 >> 1) << 3;         // k offset (0/8)
    const int b_ro = ((lm8 >> 1) << 3) + l8;  // row offset within n16 pair
    const int b_co = (lm8 & 1) << 3;          // k offset (0/8)

    for (int ch = 0; ch < NCH; ch++) {
        const int buf = ch % 3;
        cp_wait<1>();
        __syncthreads();

        const __half* as = Asm + buf * STG_H;
        const __half* bs = Bsm + buf * STG_H;

        #pragma unroll
        for (int ks = 0; ks < 2; ks++) {
            uint32_t a[4][4], b[4][2];
            #pragma unroll
            for (int mt = 0; mt < 4; mt++)
                ldmatrix_x4(a[mt],
                    smem_u32(as + (wm + mt * 16 + a_ro) * PH + ks * 16 + a_co));
            #pragma unroll
            for (int np = 0; np < 2; np++) {
                uint32_t r[4];
                ldmatrix_x4(r,
                    smem_u32(bs + (wn + np * 16 + b_ro) * PH + ks * 16 + b_co));
                b[2*np    ][0] = r[0]; b[2*np    ][1] = r[1];
                b[2*np + 1][0] = r[2]; b[2*np + 1][1] = r[3];
            }
            #pragma unroll
            for (int mt = 0; mt < 4; mt++)
                #pragma unroll
                for (int nt = 0; nt < 4; nt++)
                    mma_f16(c[mt][nt], a[mt], b[nt]);
        }
        __syncthreads();

        if (ch + 2 < NCH) load_stage((ch + 2) % 3, ch + 2);
        else              cp_commit();
    }

    // epilogue
    #pragma unroll
    for (int mt = 0; mt < 4; mt++) {
        #pragma unroll
        for (int half_ = 0; half_ < 2; half_++) {
            const int gm = m0 + wm + mt * 16 + qr + half_ * 8;
            #pragma unroll
            for (int nt = 0; nt < 4; nt++) {
                const int col = n0 + wn + nt * 8 + qc * 2;
                float v0 = c[mt][nt][half_ * 2 + 0] + bias[col];
                float v1 = c[mt][nt][half_ * 2 + 1] + bias[col + 1];
                if (ACT == 1) { v0 = gelu_exact(v0); v1 = gelu_exact(v1); }
                if (OUT == 0) {
                    const float2 rv = *(const float2*)&R[(size_t)gm * Mout + col];
                    *(float2*)((float*)Cout + (size_t)gm * Mout + col) =
                        make_float2(v0 + rv.x, v1 + rv.y);
                } else if (OUT == 1) {
                    *(__half2*)((__half*)Cout + (size_t)gm * Mout + col) =
                        __floats2half2_rn(v0, v1);
                } else {
                    // transposed V: vt[b][col][s], b = gm>>11, s = gm&2047
                    const int bb = gm >> 11, s = gm & 2047;
                    __half* vt = (__half*)Cout;
                    vt[((size_t)bb * DM + col    ) * SEQ + s] = __float2half_rn(v0);
                    vt[((size_t)bb * DM + col + 1) * SEQ + s] = __float2half_rn(v1);
                }
            }
        }
    }
}

// ---------------- fp16 mma flash attention (ldmatrix) ----------------------
// CTA: 64 q rows, 4 warps (16 rows each), KV tiles of 64, double-buffered.
// Tiles: Qs/Ks [row][dk] pitch 72 halfs; Vs = V^T [dk][kv] pitch 72 halfs.
#define PT 72
#define T_H (64 * PT)
#define ATTN_SMEM ((T_H + 2 * T_H + 2 * T_H) * 2 + 2 * 64 * 4)

__global__ void __launch_bounds__(128)
attn_kernel(const __half* __restrict__ Q, const __half* __restrict__ K,
            const __half* __restrict__ Vt, const int* __restrict__ mask,
            __half* __restrict__ O)
{
    extern __shared__ __half asm_[];
    __half* Qs = asm_;
    __half* Ks = asm_ + T_H;
    __half* Vs = asm_ + 3 * T_H;
    int*    mk = (int*)(asm_ + 5 * T_H);

    const int tid  = threadIdx.x;
    const int lane = tid & 31, wid = tid >> 5;
    const int qr = lane >> 2, qc = lane & 3;
    const int lm8 = lane >> 3, l8 = lane & 7;
    const int wm = wid * 16;
    const int b  = blockIdx.z, hh = blockIdx.y;
    const int q0 = blockIdx.x * 64;
    const int bS = b * SEQ;
    const int hoff = hh * DKH;

    const int lrow = tid >> 1;            // 0..63
    const int lseg = (tid & 1) * 32;      // halfs

    {
        const __half* src = Q + (size_t)(bS + q0 + lrow) * DM + hoff + lseg;
        uint32_t dst = smem_u32(Qs + lrow * PT + lseg);
        #pragma unroll
        for (int u = 0; u < 4; u++) cp_async16(dst + u * 16, src + u * 8);
        cp_commit();
    }

    // V^T base for this (batch, head): vt[b][col][s] with col stride SEQ
    const __half* VtBase = Vt + ((size_t)b * DM + hoff) * SEQ;

    auto load_kv = [&](int buf, int kv0) {
        const __half* ks = K + (size_t)(bS + kv0 + lrow) * DM + hoff + lseg;
        const __half* vs = VtBase + (size_t)lrow * SEQ + kv0 + lseg;
        uint32_t dk = smem_u32(Ks + buf * T_H + lrow * PT + lseg);
        uint32_t dv = smem_u32(Vs + buf * T_H + lrow * PT + lseg);
        #pragma unroll
        for (int u = 0; u < 4; u++) {
            cp_async16(dk + u * 16, ks + u * 8);
            cp_async16(dv + u * 16, vs + u * 8);
        }
        if (tid < 16)
            cp_async16(smem_u32(mk + buf * 64 + tid * 4), mask + bS + kv0 + tid * 4);
    };

    load_kv(0, 0);
    cp_commit();
    cp_wait<0>();
    __syncthreads();

    const int a_ro = ((lm8 & 1) << 3) + l8;
    const int a_co = (lm8 >> 1) << 3;
    const int b_ro = ((lm8 >> 1) << 3) + l8;
    const int b_co = (lm8 & 1) << 3;

    // preload Q fragments: 4 k16-steps over dk=64
    uint32_t a_q[4][4];
    #pragma unroll
    for (int ks = 0; ks < 4; ks++)
        ldmatrix_x4(a_q[ks], smem_u32(Qs + (wm + a_ro) * PT + ks * 16 + a_co));

    float c_o[8][4];
    #pragma unroll
    for (int nt = 0; nt < 8; nt++)
        #pragma unroll
        for (int e = 0; e < 4; e++) c_o[nt][e] = 0.f;
    float m0r = -1e30f, m1r = -1e30f, l0r = 0.f, l1r = 0.f;

    const int NT = SEQ / 64;
    for (int t = 0; t < NT; t++) {
        const int buf = t & 1;
        if (t + 1 < NT) { load_kv(buf ^ 1, (t + 1) * 64); cp_commit(); }

        // ---- S = Q K^T ----
        float c_s[8][4];
        #pragma unroll
        for (int nt = 0; nt < 8; nt++)
            #pragma unroll
            for (int e = 0; e < 4; e++) c_s[nt][e] = 0.f;

        const __half* kb = Ks + buf * T_H;
        #pragma unroll
        for (int ks = 0; ks < 4; ks++) {
            uint32_t bb[8][2];
            #pragma unroll
            for (int np = 0; np < 4; np++) {
                uint32_t r[4];
                ldmatrix_x4(r, smem_u32(kb + (np * 16 + b_ro) * PT + ks * 16 + b_co));
                bb[2*np    ][0] = r[0]; bb[2*np    ][1] = r[1];
                bb[2*np + 1][0] = r[2]; bb[2*np + 1][1] = r[3];
            }
            #pragma unroll
            for (int nt = 0; nt < 8; nt++)
                mma_f16(c_s[nt], a_q[ks], bb[nt]);
        }

        // ---- masked scale + online softmax ----
        float mx0 = -1e30f, mx1 = -1e30f;
        #pragma unroll
        for (int nt = 0; nt < 8; nt++) {
            const int c0 = nt * 8 + qc * 2;
            c_s[nt][0] = mk[buf * 64 + c0    ] ? c_s[nt][0] * 0.125f : -1e9f;
            c_s[nt][1] = mk[buf * 64 + c0 + 1] ? c_s[nt][1] * 0.125f : -1e9f;
            c_s[nt][2] = mk[buf * 64 + c0    ] ? c_s[nt][2] * 0.125f : -1e9f;
            c_s[nt][3] = mk[buf * 64 + c0 + 1] ? c_s[nt][3] * 0.125f : -1e9f;
            mx0 = fmaxf(mx0, fmaxf(c_s[nt][0], c_s[nt][1]));
            mx1 = fmaxf(mx1, fmaxf(c_s[nt][2], c_s[nt][3]));
        }
        #pragma unroll
        for (int off = 1; off < 4; off <<= 1) {
            mx0 = fmaxf(mx0, __shfl_xor_sync(0xffffffffu, mx0, off));
            mx1 = fmaxf(mx1, __shfl_xor_sync(0xffffffffu, mx1, off));
        }
        const float mn0 = fmaxf(m0r, mx0), mn1 = fmaxf(m1r, mx1);
        const float al0 = __expf(m0r - mn0), al1 = __expf(m1r - mn1);
        float s0 = 0.f, s1 = 0.f;
        #pragma unroll
        for (int nt = 0; nt < 8; nt++) {
            c_s[nt][0] = __expf(c_s[nt][0] - mn0);
            c_s[nt][1] = __expf(c_s[nt][1] - mn0);
            c_s[nt][2] = __expf(c_s[nt][2] - mn1);
            c_s[nt][3] = __expf(c_s[nt][3] - mn1);
            s0 += c_s[nt][0] + c_s[nt][1];
            s1 += c_s[nt][2] + c_s[nt][3];
        }
        #pragma unroll
        for (int off = 1; off < 4; off <<= 1) {
            s0 += __shfl_xor_sync(0xffffffffu, s0, off);
            s1 += __shfl_xor_sync(0xffffffffu, s1, off);
        }
        l0r = l0r * al0 + s0;  m0r = mn0;
        l1r = l1r * al1 + s1;  m1r = mn1;
        #pragma unroll
        for (int nt = 0; nt < 8; nt++) {
            c_o[nt][0] *= al0; c_o[nt][1] *= al0;
            c_o[nt][2] *= al1; c_o[nt][3] *= al1;
        }

        // ---- P fragments (pure register pack: C-frag -> A-frag) ----
        uint32_t ap[4][4];
        #pragma unroll
        for (int ks = 0; ks < 4; ks++) {
            ap[ks][0] = pack_h2(c_s[2*ks    ][0], c_s[2*ks    ][1]);
            ap[ks][1] = pack_h2(c_s[2*ks    ][2], c_s[2*ks    ][3]);
            ap[ks][2] = pack_h2(c_s[2*ks + 1][0], c_s[2*ks + 1][1]);
            ap[ks][3] = pack_h2(c_s[2*ks + 1][2], c_s[2*ks + 1][3]);
        }

        // ---- O += P V  (V^T tiles: [dk][kv]) ----
        const __half* vb = Vs + buf * T_H;
        #pragma unroll
        for (int ks = 0; ks < 4; ks++) {
            uint32_t bb[8][2];
            #pragma unroll
            for (int np = 0; np < 4; np++) {
                uint32_t r[4];
                ldmatrix_x4(r, smem_u32(vb + (np * 16 + b_ro) * PT + ks * 16 + b_co));
                bb[2*np    ][0] = r[0]; bb[2*np    ][1] = r[1];
                bb[2*np + 1][0] = r[2]; bb[2*np + 1][1] = r[3];
            }
            #pragma unroll
            for (int nt = 0; nt < 8; nt++)
                mma_f16(c_o[nt], ap[ks], bb[nt]);
        }

        if (t + 1 < NT) cp_wait<0>();
        __syncthreads();
    }

    // ---- epilogue (fp16 att output) ----
    const float i0 = 1.f / l0r, i1 = 1.f / l1r;
    #pragma unroll
    for (int nt = 0; nt < 8; nt++) {
        const size_t r0 = (size_t)(bS + q0 + wm + qr);
        const int col = hoff + nt * 8 + qc * 2;
        *(__half2*)&O[r0 * DM + col] =
            __floats2half2_rn(c_o[nt][0] * i0, c_o[nt][1] * i0);
        *(__half2*)&O[(r0 + 8) * DM + col] =
            __floats2half2_rn(c_o[nt][2] * i1, c_o[nt][3] * i1);
    }
}

// ---------------- launch ---------------------------------------------------
extern "C" void kernel_launch(void* const* d_in, const int* in_sizes, int n_in,
                              void* d_out, int out_size)
{
    const float* x    = (const float*)d_in[0];
    const int*   mask = (const int*)  d_in[1];
    const float* Wq   = (const float*)d_in[2];
    const float* bq   = (const float*)d_in[3];
    const float* Wk   = (const float*)d_in[4];
    const float* bk   = (const float*)d_in[5];
    const float* Wv   = (const float*)d_in[6];
    const float* bv   = (const float*)d_in[7];
    const float* Wo   = (const float*)d_in[8];
    const float* bo   = (const float*)d_in[9];
    const float* W1   = (const float*)d_in[10];
    const float* b1   = (const float*)d_in[11];
    const float* W2   = (const float*)d_in[12];
    const float* b2   = (const float*)d_in[13];
    const float* g1   = (const float*)d_in[14];
    const float* be1  = (const float*)d_in[15];
    const float* g2   = (const float*)d_in[16];
    const float* be2  = (const float*)d_in[17];
    float* out = (float*)d_out;

    __half *h, *q, *k, *vt, *att, *h2, *ff;
    float  *x1;
    __half *wqt, *wkt, *wvt, *wot, *w1t, *w2t;
    cudaGetSymbolAddress((void**)&h,   g_h);
    cudaGetSymbolAddress((void**)&q,   g_q);
    cudaGetSymbolAddress((void**)&k,   g_k);
    cudaGetSymbolAddress((void**)&vt,  g_vt);
    cudaGetSymbolAddress((void**)&att, g_att);
    cudaGetSymbolAddress((void**)&x1,  g_x1);
    cudaGetSymbolAddress((void**)&h2,  g_h2);
    cudaGetSymbolAddress((void**)&ff,  g_ff);
    cudaGetSymbolAddress((void**)&wqt, g_wqt);
    cudaGetSymbolAddress((void**)&wkt, g_wkt);
    cudaGetSymbolAddress((void**)&wvt, g_wvt);
    cudaGetSymbolAddress((void**)&wot, g_wot);
    cudaGetSymbolAddress((void**)&w1t, g_w1t);
    cudaGetSymbolAddress((void**)&w2t, g_w2t);

    cudaFuncSetAttribute(attn_kernel,
                         cudaFuncAttributeMaxDynamicSharedMemorySize, ATTN_SMEM);
    cudaFuncSetAttribute(mma_gemm<0, 0>,
                         cudaFuncAttributeMaxDynamicSharedMemorySize, GEMM_SMEM);
    cudaFuncSetAttribute(mma_gemm<0, 1>,
                         cudaFuncAttributeMaxDynamicSharedMemorySize, GEMM_SMEM);
    cudaFuncSetAttribute(mma_gemm<0, 2>,
                         cudaFuncAttributeMaxDynamicSharedMemorySize, GEMM_SMEM);
    cudaFuncSetAttribute(mma_gemm<1, 1>,
                         cudaFuncAttributeMaxDynamicSharedMemorySize, GEMM_SMEM);

    const dim3 tb(32, 8);
    tr_kernel<<<dim3(DM / 32, DM / 32), tb>>>(Wq, wqt, DM, DM);
    tr_kernel<<<dim3(DM / 32, DM / 32), tb>>>(Wk, wkt, DM, DM);
    tr_kernel<<<dim3(DM / 32, DM / 32), tb>>>(Wv, wvt, DM, DM);
    tr_kernel<<<dim3(DM / 32, DM / 32), tb>>>(Wo, wot, DM, DM);
    tr_kernel<<<dim3(DFF / 32, DM / 32), tb>>>(W1, w1t, DM, DFF);
    tr_kernel<<<dim3(DM / 32, DFF / 32), tb>>>(W2, w2t, DFF, DM);

    ln_kernel<<<NTOK, 256>>>(x, g1, be1, h);
    mma_gemm<0, 1><<<dim3(DM / 128, NTOK / 128), 256, GEMM_SMEM>>>(h, wqt, bq, nullptr, q, DM, DM);
    mma_gemm<0, 1><<<dim3(DM / 128, NTOK / 128), 256, GEMM_SMEM>>>(h, wkt, bk, nullptr, k, DM, DM);
    mma_gemm<0, 2><<<dim3(DM / 128, NTOK / 128), 256, GEMM_SMEM>>>(h, wvt, bv, nullptr, vt, DM, DM);
    attn_kernel<<<dim3(SEQ / 64, NH, NB), 128, ATTN_SMEM>>>(q, k, vt, mask, att);
    mma_gemm<0, 0><<<dim3(DM / 128, NTOK / 128), 256, GEMM_SMEM>>>(att, wot, bo, x, x1, DM, DM);
    ln_kernel<<<NTOK, 256>>>(x1, g2, be2, h2);
    mma_gemm<1, 1><<<dim3(DFF / 128, NTOK / 128), 256, GEMM_SMEM>>>(h2, w1t, b1, nullptr, ff, DM, DFF);
    mma_gemm<0, 0><<<dim3(DM / 128, NTOK / 128), 256, GEMM_SMEM>>>(ff, w2t, b2, x1, out, DFF, DM);
}

// round 10
// speedup vs baseline: 5.4999x; 1.0387x over previous
#include <cuda_runtime.h>
#include <cuda_fp16.h>
#include <math.h>
#include <stdint.h>

#define NTOK 8192
#define DM   1024
#define DFF  4096
#define SEQ  2048
#define NB   4
#define NH   16
#define DKH  64

// ---------------- scratch (device globals: allocation-guard safe) ----------
__device__ __half g_h  [(size_t)NTOK * DM];
__device__ __half g_q  [(size_t)NTOK * DM];
__device__ __half g_k  [(size_t)NTOK * DM];
__device__ __half g_vt [(size_t)NB * DM * SEQ];   // V transposed: [b][col][s]
__device__ __half g_att[(size_t)NTOK * DM];
__device__ float  g_x1 [(size_t)NTOK * DM];
__device__ __half g_h2 [(size_t)NTOK * DM];
__device__ __half g_ff [(size_t)NTOK * DFF];
__device__ __half g_wqkvt[(size_t)3 * DM * DM];   // concat W{q,k,v}^T
__device__ __half g_wot[(size_t)DM * DM];
__device__ __half g_w1t[(size_t)DFF * DM];
__device__ __half g_w2t[(size_t)DM * DFF];

// ---------------- helpers ---------------------------------------------------
__device__ __forceinline__ uint32_t smem_u32(const void* p) {
    uint32_t a;
    asm("{ .reg .u64 t; cvta.to.shared.u64 t, %1; cvt.u32.u64 %0, t; }"
        : "=r"(a) : "l"(p));
    return a;
}
__device__ __forceinline__ void cp_async16(uint32_t dst, const void* src) {
    asm volatile("cp.async.cg.shared.global [%0], [%1], 16;" :: "r"(dst), "l"(src));
}
__device__ __forceinline__ void cp_commit() {
    asm volatile("cp.async.commit_group;" ::: "memory");
}
template <int N>
__device__ __forceinline__ void cp_wait() {
    asm volatile("cp.async.wait_group %0;" :: "n"(N) : "memory");
}
__device__ __forceinline__ void ldmatrix_x4(uint32_t* r, uint32_t addr) {
    asm volatile("ldmatrix.sync.aligned.m8n8.x4.shared.b16 {%0,%1,%2,%3}, [%4];"
                 : "=r"(r[0]), "=r"(r[1]), "=r"(r[2]), "=r"(r[3]) : "r"(addr));
}
__device__ __forceinline__ void mma_f16(float* c, const uint32_t* a, const uint32_t* b) {
    asm volatile(
        "mma.sync.aligned.m16n8k16.row.col.f32.f16.f16.f32 "
        "{%0,%1,%2,%3}, {%4,%5,%6,%7}, {%8,%9}, {%0,%1,%2,%3};"
        : "+f"(c[0]), "+f"(c[1]), "+f"(c[2]), "+f"(c[3])
        : "r"(a[0]), "r"(a[1]), "r"(a[2]), "r"(a[3]), "r"(b[0]), "r"(b[1]));
}
__device__ __forceinline__ uint32_t pack_h2(float lo, float hi) {
    __half2 h = __floats2half2_rn(lo, hi);
    return *(uint32_t*)&h;
}
__device__ __forceinline__ float gelu_exact(float v)
{
    return 0.5f * v * (1.0f + erff(v * 0.70710678118654752f));
}

// ---------------- weight transpose  Wt[m, k] = fp16(W[k, m]) ---------------
__global__ void __launch_bounds__(256)
tr_kernel(const float* __restrict__ in, __half* __restrict__ out, int rows, int cols)
{
    __shared__ float t[32][33];
    const int x  = blockIdx.x * 32 + threadIdx.x;
    const int y0 = blockIdx.y * 32;
    #pragma unroll
    for (int j = threadIdx.y; j < 32; j += 8)
        t[j][threadIdx.x] = in[(size_t)(y0 + j) * cols + x];
    __syncthreads();
    const int ox  = y0 + threadIdx.x;
    const int oy0 = blockIdx.x * 32;
    #pragma unroll
    for (int j = threadIdx.y; j < 32; j += 8)
        out[(size_t)(oy0 + j) * rows + ox] = __float2half_rn(t[threadIdx.x][j]);
}

// ---------------- LayerNorm (fp32 in -> fp16 out; only feeds GEMMs) --------
__global__ void __launch_bounds__(256)
ln_kernel(const float* __restrict__ x, const float* __restrict__ gam,
          const float* __restrict__ bet, __half* __restrict__ out)
{
    const int row = blockIdx.x;
    const float4 v = ((const float4*)(x + (size_t)row * DM))[threadIdx.x];
    float s = v.x + v.y + v.z + v.w;
    float q = v.x*v.x + v.y*v.y + v.z*v.z + v.w*v.w;
    #pragma unroll
    for (int o = 16; o; o >>= 1) {
        s += __shfl_xor_sync(0xffffffffu, s, o);
        q += __shfl_xor_sync(0xffffffffu, q, o);
    }
    __shared__ float ss[8], sq[8];
    const int w = threadIdx.x >> 5, l = threadIdx.x & 31;
    if (l == 0) { ss[w] = s; sq[w] = q; }
    __syncthreads();
    if (w == 0) {
        s = (l < 8) ? ss[l] : 0.f;
        q = (l < 8) ? sq[l] : 0.f;
        #pragma unroll
        for (int o = 4; o; o >>= 1) {
            s += __shfl_xor_sync(0xffffffffu, s, o);
            q += __shfl_xor_sync(0xffffffffu, q, o);
        }
        if (l == 0) { ss[0] = s; sq[0] = q; }
    }
    __syncthreads();
    const float mean = ss[0] * (1.f / DM);
    const float var  = sq[0] * (1.f / DM) - mean * mean;
    const float rstd = rsqrtf(var + 1e-5f);
    const float4 g4 = ((const float4*)gam)[threadIdx.x];
    const float4 b4 = ((const float4*)bet)[threadIdx.x];
    __half2* o2 = (__half2*)(out + (size_t)row * DM);
    o2[threadIdx.x * 2    ] = __floats2half2_rn((v.x - mean) * rstd * g4.x + b4.x,
                                                (v.y - mean) * rstd * g4.y + b4.y);
    o2[threadIdx.x * 2 + 1] = __floats2half2_rn((v.z - mean) * rstd * g4.z + b4.z,
                                                (v.w - mean) * rstd * g4.w + b4.w);
}

// ---------------- fp16 mma GEMM (3-stage cp.async + ldmatrix) --------------
// C[NTOK, Mout] = A[NTOK, K] @ W[K, Mout] + bias (+gelu)(+res)
// OUT: 0 = fp32 (+residual), 1 = fp16, 3 = fused QKV (writes g_q/g_k/g_vt)
#define PH 40                     // halfs per smem row (80B pitch)
#define STG_H (128 * PH)          // halfs per operand per stage
#define GEMM_SMEM (3 * 2 * STG_H * 2)

template <int ACT, int OUT>
__global__ void __launch_bounds__(256, 2)
mma_gemm(const __half* __restrict__ A, const __half* __restrict__ Bt,
         const float* __restrict__ bias, const float* __restrict__ bias2,
         const float* __restrict__ bias3, const float* __restrict__ R,
         void* __restrict__ Cout, int K, int Mout)
{
    extern __shared__ __half hsm[];
    __half* Asm = hsm;
    __half* Bsm = hsm + 3 * STG_H;

    const int tid  = threadIdx.x;
    const int lane = tid & 31, wid = tid >> 5;
    const int wm = (wid >> 2) * 64;
    const int wn = (wid & 3) * 32;
    const int qr = lane >> 2, qc = lane & 3;
    const int lm8 = lane >> 3;
    const int l8  = lane & 7;
    const int m0 = blockIdx.y * 128, n0 = blockIdx.x * 128;

    float c[4][4][4];
    #pragma unroll
    for (int i = 0; i < 4; i++)
        #pragma unroll
        for (int j = 0; j < 4; j++)
            #pragma unroll
            for (int e = 0; e < 4; e++) c[i][j][e] = 0.f;

    const int lrow = tid >> 1;
    const int lseg = (tid & 1) * 16;
    const __half* Ap = A  + (size_t)(m0 + lrow) * K + lseg;
    const __half* Bp = Bt + (size_t)(n0 + lrow) * K + lseg;

    const int NCH = K >> 5;

    auto load_stage = [&](int st, int ch) {
        const int koff = ch * 32;
        __half* as = Asm + st * STG_H + lrow * PH + lseg;
        __half* bs = Bsm + st * STG_H + lrow * PH + lseg;
        cp_async16(smem_u32(as),     Ap + koff);
        cp_async16(smem_u32(as + 8), Ap + koff + 8);
        cp_async16(smem_u32(bs),     Bp + koff);
        cp_async16(smem_u32(bs + 8), Bp + koff + 8);
        cp_commit();
    };

    load_stage(0, 0);
    load_stage(1, 1);

    const int a_ro = ((lm8 & 1) << 3) + l8;
    const int a_co = (lm8 >> 1) << 3;
    const int b_ro = ((lm8 >> 1) << 3) + l8;
    const int b_co = (lm8 & 1) << 3;

    for (int ch = 0; ch < NCH; ch++) {
        const int buf = ch % 3;
        cp_wait<1>();
        __syncthreads();

        // issue next-next stage BEFORE compute: true depth-2 latency hiding.
        // Writes buf (ch+2)%3 == (ch-1)%3, last read at iter ch-1, ordered by
        // the barrier above. No trailing barrier needed.
        if (ch + 2 < NCH) load_stage((ch + 2) % 3, ch + 2);
        else              cp_commit();

        const __half* as = Asm + buf * STG_H;
        const __half* bs = Bsm + buf * STG_H;

        #pragma unroll
        for (int ks = 0; ks < 2; ks++) {
            uint32_t a[4][4], b[4][2];
            #pragma unroll
            for (int mt = 0; mt < 4; mt++)
                ldmatrix_x4(a[mt],
                    smem_u32(as + (wm + mt * 16 + a_ro) * PH + ks * 16 + a_co));
            #pragma unroll
            for (int np = 0; np < 2; np++) {
                uint32_t r[4];
                ldmatrix_x4(r,
                    smem_u32(bs + (wn + np * 16 + b_ro) * PH + ks * 16 + b_co));
                b[2*np    ][0] = r[0]; b[2*np    ][1] = r[1];
                b[2*np + 1][0] = r[2]; b[2*np + 1][1] = r[3];
            }
            #pragma unroll
            for (int mt = 0; mt < 4; mt++)
                #pragma unroll
                for (int nt = 0; nt < 4; nt++)
                    mma_f16(c[mt][nt], a[mt], b[nt]);
        }
    }

    // ---- epilogue ----
    if (OUT == 3) {
        // fused QKV: segment (q/k/v) is uniform per CTA
        const int seg   = n0 >> 10;
        const int nbase = (n0 & 1023) + wn;
        const float* bp = (seg == 0) ? bias : (seg == 1 ? bias2 : bias3);
        #pragma unroll
        for (int mt = 0; mt < 4; mt++) {
            #pragma unroll
            for (int half_ = 0; half_ < 2; half_++) {
                const int gm = m0 + wm + mt * 16 + qr + half_ * 8;
                #pragma unroll
                for (int nt = 0; nt < 4; nt++) {
                    const int col = nbase + nt * 8 + qc * 2;
                    const float v0 = c[mt][nt][half_ * 2 + 0] + bp[col];
                    const float v1 = c[mt][nt][half_ * 2 + 1] + bp[col + 1];
                    if (seg == 0) {
                        *(__half2*)&g_q[(size_t)gm * DM + col] = __floats2half2_rn(v0, v1);
                    } else if (seg == 1) {
                        *(__half2*)&g_k[(size_t)gm * DM + col] = __floats2half2_rn(v0, v1);
                    } else {
                        const int bb = gm >> 11, s = gm & 2047;
                        g_vt[((size_t)bb * DM + col    ) * SEQ + s] = __float2half_rn(v0);
                        g_vt[((size_t)bb * DM + col + 1) * SEQ + s] = __float2half_rn(v1);
                    }
                }
            }
        }
    } else {
        #pragma unroll
        for (int mt = 0; mt < 4; mt++) {
            #pragma unroll
            for (int half_ = 0; half_ < 2; half_++) {
                const int gm = m0 + wm + mt * 16 + qr + half_ * 8;
                #pragma unroll
                for (int nt = 0; nt < 4; nt++) {
                    const int col = n0 + wn + nt * 8 + qc * 2;
                    float v0 = c[mt][nt][half_ * 2 + 0] + bias[col];
                    float v1 = c[mt][nt][half_ * 2 + 1] + bias[col + 1];
                    if (ACT == 1) { v0 = gelu_exact(v0); v1 = gelu_exact(v1); }
                    if (OUT == 0) {
                        const float2 rv = *(const float2*)&R[(size_t)gm * Mout + col];
                        *(float2*)((float*)Cout + (size_t)gm * Mout + col) =
                            make_float2(v0 + rv.x, v1 + rv.y);
                    } else {
                        *(__half2*)((__half*)Cout + (size_t)gm * Mout + col) =
                            __floats2half2_rn(v0, v1);
                    }
                }
            }
        }
    }
}

// ---------------- fp16 mma flash attention (ldmatrix) ----------------------
#define PT 72
#define T_H (64 * PT)
#define ATTN_SMEM ((T_H + 2 * T_H + 2 * T_H) * 2 + 2 * 64 * 4)

__global__ void __launch_bounds__(128)
attn_kernel(const __half* __restrict__ Q, const __half* __restrict__ K,
            const __half* __restrict__ Vt, const int* __restrict__ mask,
            __half* __restrict__ O)
{
    extern __shared__ __half asm_[];
    __half* Qs = asm_;
    __half* Ks = asm_ + T_H;
    __half* Vs = asm_ + 3 * T_H;
    int*    mk = (int*)(asm_ + 5 * T_H);

    const int tid  = threadIdx.x;
    const int lane = tid & 31, wid = tid >> 5;
    const int qr = lane >> 2, qc = lane & 3;
    const int lm8 = lane >> 3, l8 = lane & 7;
    const int wm = wid * 16;
    const int b  = blockIdx.z, hh = blockIdx.y;
    const int q0 = blockIdx.x * 64;
    const int bS = b * SEQ;
    const int hoff = hh * DKH;

    const int lrow = tid >> 1;
    const int lseg = (tid & 1) * 32;

    {
        const __half* src = Q + (size_t)(bS + q0 + lrow) * DM + hoff + lseg;
        uint32_t dst = smem_u32(Qs + lrow * PT + lseg);
        #pragma unroll
        for (int u = 0; u < 4; u++) cp_async16(dst + u * 16, src + u * 8);
        cp_commit();
    }

    const __half* VtBase = Vt + ((size_t)b * DM + hoff) * SEQ;

    auto load_kv = [&](int buf, int kv0) {
        const __half* ks = K + (size_t)(bS + kv0 + lrow) * DM + hoff + lseg;
        const __half* vs = VtBase + (size_t)lrow * SEQ + kv0 + lseg;
        uint32_t dk = smem_u32(Ks + buf * T_H + lrow * PT + lseg);
        uint32_t dv = smem_u32(Vs + buf * T_H + lrow * PT + lseg);
        #pragma unroll
        for (int u = 0; u < 4; u++) {
            cp_async16(dk + u * 16, ks + u * 8);
            cp_async16(dv + u * 16, vs + u * 8);
        }
        if (tid < 16)
            cp_async16(smem_u32(mk + buf * 64 + tid * 4), mask + bS + kv0 + tid * 4);
    };

    load_kv(0, 0);
    cp_commit();
    cp_wait<0>();
    __syncthreads();

    const int a_ro = ((lm8 & 1) << 3) + l8;
    const int a_co = (lm8 >> 1) << 3;
    const int b_ro = ((lm8 >> 1) << 3) + l8;
    const int b_co = (lm8 & 1) << 3;

    uint32_t a_q[4][4];
    #pragma unroll
    for (int ks = 0; ks < 4; ks++)
        ldmatrix_x4(a_q[ks], smem_u32(Qs + (wm + a_ro) * PT + ks * 16 + a_co));

    float c_o[8][4];
    #pragma unroll
    for (int nt = 0; nt < 8; nt++)
        #pragma unroll
        for (int e = 0; e < 4; e++) c_o[nt][e] = 0.f;
    float m0r = -1e30f, m1r = -1e30f, l0r = 0.f, l1r = 0.f;

    const int NT = SEQ / 64;
    for (int t = 0; t < NT; t++) {
        const int buf = t & 1;
        if (t + 1 < NT) { load_kv(buf ^ 1, (t + 1) * 64); cp_commit(); }

        float c_s[8][4];
        #pragma unroll
        for (int nt = 0; nt < 8; nt++)
            #pragma unroll
            for (int e = 0; e < 4; e++) c_s[nt][e] = 0.f;

        const __half* kb = Ks + buf * T_H;
        #pragma unroll
        for (int ks = 0; ks < 4; ks++) {
            uint32_t bb[8][2];
            #pragma unroll
            for (int np = 0; np < 4; np++) {
                uint32_t r[4];
                ldmatrix_x4(r, smem_u32(kb + (np * 16 + b_ro) * PT + ks * 16 + b_co));
                bb[2*np    ][0] = r[0]; bb[2*np    ][1] = r[1];
                bb[2*np + 1][0] = r[2]; bb[2*np + 1][1] = r[3];
            }
            #pragma unroll
            for (int nt = 0; nt < 8; nt++)
                mma_f16(c_s[nt], a_q[ks], bb[nt]);
        }

        float mx0 = -1e30f, mx1 = -1e30f;
        #pragma unroll
        for (int nt = 0; nt < 8; nt++) {
            const int c0 = nt * 8 + qc * 2;
            c_s[nt][0] = mk[buf * 64 + c0    ] ? c_s[nt][0] * 0.125f : -1e9f;
            c_s[nt][1] = mk[buf * 64 + c0 + 1] ? c_s[nt][1] * 0.125f : -1e9f;
            c_s[nt][2] = mk[buf * 64 + c0    ] ? c_s[nt][2] * 0.125f : -1e9f;
            c_s[nt][3] = mk[buf * 64 + c0 + 1] ? c_s[nt][3] * 0.125f : -1e9f;
            mx0 = fmaxf(mx0, fmaxf(c_s[nt][0], c_s[nt][1]));
            mx1 = fmaxf(mx1, fmaxf(c_s[nt][2], c_s[nt][3]));
        }
        #pragma unroll
        for (int off = 1; off < 4; off <<= 1) {
            mx0 = fmaxf(mx0, __shfl_xor_sync(0xffffffffu, mx0, off));
            mx1 = fmaxf(mx1, __shfl_xor_sync(0xffffffffu, mx1, off));
        }
        const float mn0 = fmaxf(m0r, mx0), mn1 = fmaxf(m1r, mx1);
        const float al0 = __expf(m0r - mn0), al1 = __expf(m1r - mn1);
        float s0 = 0.f, s1 = 0.f;
        #pragma unroll
        for (int nt = 0; nt < 8; nt++) {
            c_s[nt][0] = __expf(c_s[nt][0] - mn0);
            c_s[nt][1] = __expf(c_s[nt][1] - mn0);
            c_s[nt][2] = __expf(c_s[nt][2] - mn1);
            c_s[nt][3] = __expf(c_s[nt][3] - mn1);
            s0 += c_s[nt][0] + c_s[nt][1];
            s1 += c_s[nt][2] + c_s[nt][3];
        }
        #pragma unroll
        for (int off = 1; off < 4; off <<= 1) {
            s0 += __shfl_xor_sync(0xffffffffu, s0, off);
            s1 += __shfl_xor_sync(0xffffffffu, s1, off);
        }
        l0r = l0r * al0 + s0;  m0r = mn0;
        l1r = l1r * al1 + s1;  m1r = mn1;
        #pragma unroll
        for (int nt = 0; nt < 8; nt++) {
            c_o[nt][0] *= al0; c_o[nt][1] *= al0;
            c_o[nt][2] *= al1; c_o[nt][3] *= al1;
        }

        uint32_t ap[4][4];
        #pragma unroll
        for (int ks = 0; ks < 4; ks++) {
            ap[ks][0] = pack_h2(c_s[2*ks    ][0], c_s[2*ks    ][1]);
            ap[ks][1] = pack_h2(c_s[2*ks    ][2], c_s[2*ks    ][3]);
            ap[ks][2] = pack_h2(c_s[2*ks + 1][0], c_s[2*ks + 1][1]);
            ap[ks][3] = pack_h2(c_s[2*ks + 1][2], c_s[2*ks + 1][3]);
        }

        const __half* vb = Vs + buf * T_H;
        #pragma unroll
        for (int ks = 0; ks < 4; ks++) {
            uint32_t bb[8][2];
            #pragma unroll
            for (int np = 0; np < 4; np++) {
                uint32_t r[4];
                ldmatrix_x4(r, smem_u32(vb + (np * 16 + b_ro) * PT + ks * 16 + b_co));
                bb[2*np    ][0] = r[0]; bb[2*np    ][1] = r[1];
                bb[2*np + 1][0] = r[2]; bb[2*np + 1][1] = r[3];
            }
            #pragma unroll
            for (int nt = 0; nt < 8; nt++)
                mma_f16(c_o[nt], ap[ks], bb[nt]);
        }

        if (t + 1 < NT) cp_wait<0>();
        __syncthreads();
    }

    const float i0 = 1.f / l0r, i1 = 1.f / l1r;
    #pragma unroll
    for (int nt = 0; nt < 8; nt++) {
        const size_t r0 = (size_t)(bS + q0 + wm + qr);
        const int col = hoff + nt * 8 + qc * 2;
        *(__half2*)&O[r0 * DM + col] =
            __floats2half2_rn(c_o[nt][0] * i0, c_o[nt][1] * i0);
        *(__half2*)&O[(r0 + 8) * DM + col] =
            __floats2half2_rn(c_o[nt][2] * i1, c_o[nt][3] * i1);
    }
}

// ---------------- launch ---------------------------------------------------
extern "C" void kernel_launch(void* const* d_in, const int* in_sizes, int n_in,
                              void* d_out, int out_size)
{
    const float* x    = (const float*)d_in[0];
    const int*   mask = (const int*)  d_in[1];
    const float* Wq   = (const float*)d_in[2];
    const float* bq   = (const float*)d_in[3];
    const float* Wk   = (const float*)d_in[4];
    const float* bk   = (const float*)d_in[5];
    const float* Wv   = (const float*)d_in[6];
    const float* bv   = (const float*)d_in[7];
    const float* Wo   = (const float*)d_in[8];
    const float* bo   = (const float*)d_in[9];
    const float* W1   = (const float*)d_in[10];
    const float* b1   = (const float*)d_in[11];
    const float* W2   = (const float*)d_in[12];
    const float* b2   = (const float*)d_in[13];
    const float* g1   = (const float*)d_in[14];
    const float* be1  = (const float*)d_in[15];
    const float* g2   = (const float*)d_in[16];
    const float* be2  = (const float*)d_in[17];
    float* out = (float*)d_out;

    __half *h, *q, *k, *vt, *att, *h2, *ff;
    float  *x1;
    __half *wqkvt, *wot, *w1t, *w2t;
    cudaGetSymbolAddress((void**)&h,     g_h);
    cudaGetSymbolAddress((void**)&q,     g_q);
    cudaGetSymbolAddress((void**)&k,     g_k);
    cudaGetSymbolAddress((void**)&vt,    g_vt);
    cudaGetSymbolAddress((void**)&att,   g_att);
    cudaGetSymbolAddress((void**)&x1,    g_x1);
    cudaGetSymbolAddress((void**)&h2,    g_h2);
    cudaGetSymbolAddress((void**)&ff,    g_ff);
    cudaGetSymbolAddress((void**)&wqkvt, g_wqkvt);
    cudaGetSymbolAddress((void**)&wot,   g_wot);
    cudaGetSymbolAddress((void**)&w1t,   g_w1t);
    cudaGetSymbolAddress((void**)&w2t,   g_w2t);

    cudaFuncSetAttribute(attn_kernel,
                         cudaFuncAttributeMaxDynamicSharedMemorySize, ATTN_SMEM);
    cudaFuncSetAttribute(mma_gemm<0, 0>,
                         cudaFuncAttributeMaxDynamicSharedMemorySize, GEMM_SMEM);
    cudaFuncSetAttribute(mma_gemm<0, 1>,
                         cudaFuncAttributeMaxDynamicSharedMemorySize, GEMM_SMEM);
    cudaFuncSetAttribute(mma_gemm<0, 3>,
                         cudaFuncAttributeMaxDynamicSharedMemorySize, GEMM_SMEM);
    cudaFuncSetAttribute(mma_gemm<1, 1>,
                         cudaFuncAttributeMaxDynamicSharedMemorySize, GEMM_SMEM);

    const dim3 tb(32, 8);
    tr_kernel<<<dim3(DM / 32, DM / 32), tb>>>(Wq, wqkvt, DM, DM);
    tr_kernel<<<dim3(DM / 32, DM / 32), tb>>>(Wk, wqkvt + (size_t)DM * DM, DM, DM);
    tr_kernel<<<dim3(DM / 32, DM / 32), tb>>>(Wv, wqkvt + (size_t)2 * DM * DM, DM, DM);
    tr_kernel<<<dim3(DM / 32, DM / 32), tb>>>(Wo, wot, DM, DM);
    tr_kernel<<<dim3(DFF / 32, DM / 32), tb>>>(W1, w1t, DM, DFF);
    tr_kernel<<<dim3(DM / 32, DFF / 32), tb>>>(W2, w2t, DFF, DM);

    ln_kernel<<<NTOK, 256>>>(x, g1, be1, h);
    // fused Q/K/V projection (writes g_q, g_k, g_vt directly)
    mma_gemm<0, 3><<<dim3(3 * DM / 128, NTOK / 128), 256, GEMM_SMEM>>>(
        h, wqkvt, bq, bk, bv, nullptr, nullptr, DM, 3 * DM);
    attn_kernel<<<dim3(SEQ / 64, NH, NB), 128, ATTN_SMEM>>>(q, k, vt, mask, att);
    mma_gemm<0, 0><<<dim3(DM / 128, NTOK / 128), 256, GEMM_SMEM>>>(
        att, wot, bo, nullptr, nullptr, x, x1, DM, DM);
    ln_kernel<<<NTOK, 256>>>(x1, g2, be2, h2);
    mma_gemm<1, 1><<<dim3(DFF / 128, NTOK / 128), 256, GEMM_SMEM>>>(
        h2, w1t, b1, nullptr, nullptr, nullptr, ff, DM, DFF);
    mma_gemm<0, 0><<<dim3(DM / 128, NTOK / 128), 256, GEMM_SMEM>>>(
        ff, w2t, b2, nullptr, nullptr, x1, out, DFF, DM);
}